// round 2
// baseline (speedup 1.0000x reference)
#include <cuda_runtime.h>
#include <cuda_bf16.h>
#include <math.h>

// Problem shapes (fixed by the reference)
#define BB 4
#define SS 4096
#define UU 1024

// Scratch (allocation-free rule: __device__ globals)
__device__ float g_pq[BB * SS * UU];
__device__ float g_pk[BB * SS * UU];
__device__ float g_pv[BB * SS * UU];
__device__ float g_kv[BB * UU * UU];
__device__ float g_o1[BB * SS * UU];

// ---------------- packed f32x2 helpers (Blackwell FFMA2 path) ----------------
__device__ __forceinline__ unsigned long long pack2(float lo, float hi) {
    unsigned long long r;
    asm("mov.b64 %0, {%1, %2};" : "=l"(r) : "f"(lo), "f"(hi));
    return r;
}
__device__ __forceinline__ void unpack2(unsigned long long v, float& lo, float& hi) {
    asm("mov.b64 {%0, %1}, %2;" : "=f"(lo), "=f"(hi) : "l"(v));
}
__device__ __forceinline__ unsigned long long ffma2(unsigned long long a,
                                                    unsigned long long b,
                                                    unsigned long long c) {
    unsigned long long d;
    asm("fma.rn.f32x2 %0, %1, %2, %3;" : "=l"(d) : "l"(a), "l"(b), "l"(c));
    return d;
}

// ---------------- tiled GEMM ----------------
// C[M,N] = A ? B  (row-major). If TRANSA == false: A is [M,K] (lda=K).
// If TRANSA == true:  A is [K,M] (lda=M), i.e. C = A^T B.
// B is [K,N] (ldb=N). Batched via blockIdx.z with element strides sA/sB/sC.
// mode: 0 = plain store, 1 = *mask[row], 2 = *mask[row] then swish.
#define BM 128
#define BN 128
#define BK 16
#define TM 8
#define TN 8
#define NTHREADS 256
#define LDS_PAD 4
#define LDA_S (BM + LDS_PAD)

template <bool TRANSA>
__global__ __launch_bounds__(NTHREADS, 2)
void gemm_kernel(const float* __restrict__ A, const float* __restrict__ B,
                 float* __restrict__ C, int M, int N, int K,
                 long long sA, long long sB, long long sC,
                 const float* __restrict__ mask, int mode) {
    __shared__ float As[BK][LDA_S];
    __shared__ float Bs[BK][BN + LDS_PAD];

    const int bz = blockIdx.z;
    A += (long long)bz * sA;
    B += (long long)bz * sB;
    C += (long long)bz * sC;

    const int m0 = blockIdx.y * BM;
    const int n0 = blockIdx.x * BN;
    const int tid = threadIdx.x;
    const int tm = (tid >> 4) * TM;   // 16 thread-rows
    const int tn = (tid & 15) * TN;   // 16 thread-cols

    unsigned long long acc[TM][TN / 2];
#pragma unroll
    for (int i = 0; i < TM; i++)
#pragma unroll
        for (int j = 0; j < TN / 2; j++) acc[i][j] = 0ull;

    for (int k0 = 0; k0 < K; k0 += BK) {
        // ---- load A tile into As[k][m] ----
        if (TRANSA) {
            // A is [K, M]: rows k0..k0+15, cols m0..m0+127 (contiguous) -> direct
#pragma unroll
            for (int it = 0; it < 2; ++it) {
                int idx = tid + it * NTHREADS;        // 0..511 float4s
                int r = idx >> 5;                     // 0..15
                int c = (idx & 31) << 2;              // 0..124
                float4 v = *reinterpret_cast<const float4*>(
                    A + (long long)(k0 + r) * M + m0 + c);
                *reinterpret_cast<float4*>(&As[r][c]) = v;
            }
        } else {
            // A is [M, K]: rows m0..m0+127, cols k0..k0+15 -> transpose into As
#pragma unroll
            for (int it = 0; it < 2; ++it) {
                int idx = tid + it * NTHREADS;        // 0..511 float4s
                int row = idx >> 2;                   // 0..127
                int c4 = (idx & 3) << 2;              // 0,4,8,12
                float4 v = *reinterpret_cast<const float4*>(
                    A + (long long)(m0 + row) * K + k0 + c4);
                As[c4 + 0][row] = v.x;
                As[c4 + 1][row] = v.y;
                As[c4 + 2][row] = v.z;
                As[c4 + 3][row] = v.w;
            }
        }
        // ---- load B tile into Bs[k][n] ----
#pragma unroll
        for (int it = 0; it < 2; ++it) {
            int idx = tid + it * NTHREADS;
            int r = idx >> 5;
            int c = (idx & 31) << 2;
            float4 v = *reinterpret_cast<const float4*>(
                B + (long long)(k0 + r) * N + n0 + c);
            *reinterpret_cast<float4*>(&Bs[r][c]) = v;
        }
        __syncthreads();

#pragma unroll
        for (int k = 0; k < BK; ++k) {
            float4 b0 = *reinterpret_cast<const float4*>(&Bs[k][tn]);
            float4 b1 = *reinterpret_cast<const float4*>(&Bs[k][tn + 4]);
            unsigned long long bb[4];
            bb[0] = pack2(b0.x, b0.y);
            bb[1] = pack2(b0.z, b0.w);
            bb[2] = pack2(b1.x, b1.y);
            bb[3] = pack2(b1.z, b1.w);
            float4 a0 = *reinterpret_cast<const float4*>(&As[k][tm]);
            float4 a1 = *reinterpret_cast<const float4*>(&As[k][tm + 4]);
            float a[TM] = {a0.x, a0.y, a0.z, a0.w, a1.x, a1.y, a1.z, a1.w};
#pragma unroll
            for (int i = 0; i < TM; i++) {
                unsigned long long ad = pack2(a[i], a[i]);
#pragma unroll
                for (int j = 0; j < TN / 2; j++)
                    acc[i][j] = ffma2(ad, bb[j], acc[i][j]);
            }
        }
        __syncthreads();
    }

    // ---- epilogue ----
#pragma unroll
    for (int i = 0; i < TM; i++) {
        int row = m0 + tm + i;
        float o[TN];
#pragma unroll
        for (int j = 0; j < TN / 2; j++) unpack2(acc[i][j], o[2 * j], o[2 * j + 1]);
        if (mode > 0) {
            float mv = mask[row];
#pragma unroll
            for (int j = 0; j < TN; j++) o[j] *= mv;
        }
        if (mode == 2) {
#pragma unroll
            for (int j = 0; j < TN; j++) o[j] = o[j] / (1.0f + expf(-o[j]));
        }
        float4 r0 = make_float4(o[0], o[1], o[2], o[3]);
        float4 r1 = make_float4(o[4], o[5], o[6], o[7]);
        float* cp = C + (long long)row * N + n0 + tn;
        *reinterpret_cast<float4*>(cp) = r0;
        *reinterpret_cast<float4*>(cp + 4) = r1;
    }
}

extern "C" void kernel_launch(void* const* d_in, const int* in_sizes, int n_in,
                              void* d_out, int out_size) {
    const float* query = (const float*)d_in[0];
    const float* key   = (const float*)d_in[1];
    const float* value = (const float*)d_in[2];
    const float* mask  = (const float*)d_in[3];
    const float* Wk    = (const float*)d_in[4];
    const float* Wv    = (const float*)d_in[5];
    const float* Wq    = (const float*)d_in[6];
    const float* Wo    = (const float*)d_in[7];
    float* out = (float*)d_out;

    float *pq, *pk, *pv, *kv, *o1;
    cudaGetSymbolAddress((void**)&pq, g_pq);
    cudaGetSymbolAddress((void**)&pk, g_pk);
    cudaGetSymbolAddress((void**)&pv, g_pv);
    cudaGetSymbolAddress((void**)&kv, g_kv);
    cudaGetSymbolAddress((void**)&o1, g_o1);

    const int M1 = BB * SS;  // 16384
    dim3 block(NTHREADS);

    // 1) projections: [16384,1024] x [1024,1024]
    dim3 gProj(UU / BN, M1 / BM, 1);
    gemm_kernel<false><<<gProj, block>>>(query, Wq, pq, M1, UU, UU, 0, 0, 0, nullptr, 0);
    gemm_kernel<false><<<gProj, block>>>(key,   Wk, pk, M1, UU, UU, 0, 0, 0, mask, 2);  // mask then swish
    gemm_kernel<false><<<gProj, block>>>(value, Wv, pv, M1, UU, UU, 0, 0, 0, mask, 1);  // mask

    // 2) kv[b] = pk[b]^T @ pv[b]  : [1024,1024] per batch, K=4096
    dim3 gKV(UU / BN, UU / BM, BB);
    gemm_kernel<true><<<gKV, block>>>(pk, pv, kv, UU, UU, SS,
                                      (long long)SS * UU, (long long)SS * UU,
                                      (long long)UU * UU, nullptr, 0);

    // 3) o1[b] = pq[b] @ kv[b] : [4096,1024] per batch, K=1024
    dim3 gQKV(UU / BN, SS / BM, BB);
    gemm_kernel<false><<<gQKV, block>>>(pq, kv, o1, SS, UU, UU,
                                        (long long)SS * UU, (long long)UU * UU,
                                        (long long)SS * UU, nullptr, 0);

    // 4) out = o1 @ Wo : [16384,1024]
    gemm_kernel<false><<<gProj, block>>>(o1, Wo, out, M1, UU, UU, 0, 0, 0, nullptr, 0);
}

// round 4
// speedup vs baseline: 2.6981x; 2.6981x over previous
#include <cuda_runtime.h>
#include <cuda_bf16.h>
#include <cstdint>
#include <string.h>
#include <math.h>

#define BBATCH 4
#define SSEQ 4096
#define UDIM 1024
#define MTOT (BBATCH*SSEQ)
typedef __nv_bfloat16 bf16;

// Tile geometry: A tiles [128 rows][40 cols pad (32 real)] bf16 ; B tiles [32 rows][136 cols pad (128 real)]
#define TA 10240
#define TBB 8704
#define STG (2*TA + 2*TBB)     // 37888 per stage (Ah, Al, Bh, Bl)
#define STAGES 3
#define SMEM_SZ (1024 + STAGES*STG)

// ---------------- device-global scratch ----------------
__device__ __align__(128) char g_qh[128*32*TA], g_ql[128*32*TA];
__device__ __align__(128) char g_kh[128*32*TA], g_kl[128*32*TA];
__device__ __align__(128) char g_vh[128*32*TA], g_vl[128*32*TA];
__device__ __align__(128) char g_wqh[8*32*TBB], g_wql[8*32*TBB];
__device__ __align__(128) char g_wkh[8*32*TBB], g_wkl[8*32*TBB];
__device__ __align__(128) char g_wvh[8*32*TBB], g_wvl[8*32*TBB];
__device__ __align__(128) char g_woh[8*32*TBB], g_wol[8*32*TBB];
__device__ __align__(128) char g_pqh[128*32*TA], g_pql[128*32*TA];
__device__ __align__(128) char g_o1h[128*32*TA], g_o1l[128*32*TA];
__device__ __align__(128) char g_pkth[4*8*128*TA], g_pktl[4*8*128*TA];   // pk^T A-layout per batch
__device__ __align__(128) char g_pvh[4*8*128*TBB], g_pvl[4*8*128*TBB];   // pv B-layout per batch
__device__ __align__(128) char g_kvh[4*8*32*TBB], g_kvl[4*8*32*TBB];     // kv B-layout per batch

// ---------------- PTX helpers ----------------
__device__ __forceinline__ uint32_t s2u(const void* p) {
    uint32_t a;
    asm("{ .reg .u64 t; cvta.to.shared.u64 t, %1; cvt.u32.u64 %0, t; }" : "=r"(a) : "l"(p));
    return a;
}
#define MBARRIER_INIT(addr, cnt) \
    asm volatile("mbarrier.init.shared.b64 [%0], %1;" :: "r"((uint32_t)(addr)), "r"((uint32_t)(cnt)) : "memory")
#define MBARRIER_EXPECT_TX(addr, bytes) \
    asm volatile("mbarrier.arrive.expect_tx.shared.b64 _, [%0], %1;" :: "r"((uint32_t)(addr)), "r"((uint32_t)(bytes)) : "memory")
#define MBARRIER_WAIT_PARITY(mbar, par) do { \
    uint32_t _m = (uint32_t)(mbar); uint32_t _p = (uint32_t)(par); uint32_t _d; \
    asm volatile("{\n\t.reg .pred p;\n\tmbarrier.try_wait.parity.acquire.cta.shared::cta.b64 p, [%1], %2;\n\tselp.b32 %0, 1, 0, p;\n\t}" \
        : "=r"(_d) : "r"(_m), "r"(_p) : "memory"); \
    if (!_d) { \
        asm volatile("{\n\t.reg .pred P1;\n\tWL_%=:\n\tmbarrier.try_wait.parity.acquire.cta.shared::cta.b64 P1, [%0], %1, 0x989680;\n\t@P1 bra.uni WD_%=;\n\tbra.uni WL_%=;\n\tWD_%=:\n\t}" \
            :: "r"(_m), "r"(_p) : "memory"); \
    } \
} while(0)

__device__ __forceinline__ void bulk_g2s(uint32_t dst, const void* src, uint32_t bytes, uint32_t mbar) {
    asm volatile("cp.async.bulk.shared::cluster.global.mbarrier::complete_tx::bytes [%0], [%1], %2, [%3];"
        :: "r"(dst), "l"(src), "r"(bytes), "r"(mbar) : "memory");
}
__device__ __forceinline__ void ldsm4(uint32_t* r, uint32_t a) {
    asm volatile("ldmatrix.sync.aligned.m8n8.x4.shared.b16 {%0,%1,%2,%3}, [%4];"
        : "=r"(r[0]), "=r"(r[1]), "=r"(r[2]), "=r"(r[3]) : "r"(a));
}
__device__ __forceinline__ void ldsm4t(uint32_t* r, uint32_t a) {
    asm volatile("ldmatrix.sync.aligned.m8n8.x4.trans.shared.b16 {%0,%1,%2,%3}, [%4];"
        : "=r"(r[0]), "=r"(r[1]), "=r"(r[2]), "=r"(r[3]) : "r"(a));
}
__device__ __forceinline__ void mma16816(float* c, const uint32_t* a, const uint32_t* b) {
    asm volatile("mma.sync.aligned.m16n8k16.row.col.f32.bf16.bf16.f32 "
        "{%0,%1,%2,%3}, {%4,%5,%6,%7}, {%8,%9}, {%0,%1,%2,%3};"
        : "+f"(c[0]), "+f"(c[1]), "+f"(c[2]), "+f"(c[3])
        : "r"(a[0]), "r"(a[1]), "r"(a[2]), "r"(a[3]), "r"(b[0]), "r"(b[1]));
}

__device__ __forceinline__ unsigned short bfraw(bf16 h) { unsigned short u; memcpy(&u, &h, 2); return u; }
__device__ __forceinline__ void split2(float x, float y, uint32_t& H, uint32_t& L) {
    bf16 hx = __float2bfloat16(x), hy = __float2bfloat16(y);
    bf16 lx = __float2bfloat16(x - __bfloat162float(hx));
    bf16 ly = __float2bfloat16(y - __bfloat162float(hy));
    H = (uint32_t)bfraw(hx) | ((uint32_t)bfraw(hy) << 16);
    L = (uint32_t)bfraw(lx) | ((uint32_t)bfraw(ly) << 16);
}

// ---------------- conversions ----------------
// activations [M][1024] f32 -> A-layout tiles [mblk][kblk 0..31][128][40]
__global__ void conv_act(const float* __restrict__ src, char* __restrict__ hi, char* __restrict__ lo) {
    int idx = blockIdx.x * 256 + threadIdx.x;   // M*128
    int m = idx >> 7;
    int k0 = (idx & 127) << 3;
    const float4* s = reinterpret_cast<const float4*>(src + ((size_t)m << 10) + k0);
    float4 a = s[0], b = s[1];
    uint32_t h[4], l[4];
    split2(a.x, a.y, h[0], l[0]); split2(a.z, a.w, h[1], l[1]);
    split2(b.x, b.y, h[2], l[2]); split2(b.z, b.w, h[3], l[3]);
    size_t tile = ((size_t)(m >> 7) * 32 + (k0 >> 5)) * TA;
    uint32_t off = (uint32_t)(m & 127) * 80 + (k0 & 31) * 2;
    *reinterpret_cast<uint4*>(hi + tile + off) = make_uint4(h[0], h[1], h[2], h[3]);
    *reinterpret_cast<uint4*>(lo + tile + off) = make_uint4(l[0], l[1], l[2], l[3]);
}
// W [1024 k][1024 n] f32 -> B-layout tiles [nblk][kblk][32][136]
__global__ void conv_w(const float* __restrict__ W, char* __restrict__ hi, char* __restrict__ lo) {
    int idx = blockIdx.x * 256 + threadIdx.x;   // 1024*128
    int k = idx >> 7;
    int n0 = (idx & 127) << 3;
    const float4* s = reinterpret_cast<const float4*>(W + ((size_t)k << 10) + n0);
    float4 a = s[0], b = s[1];
    uint32_t h[4], l[4];
    split2(a.x, a.y, h[0], l[0]); split2(a.z, a.w, h[1], l[1]);
    split2(b.x, b.y, h[2], l[2]); split2(b.z, b.w, h[3], l[3]);
    size_t tile = ((size_t)(n0 >> 7) * 32 + (k >> 5)) * TBB;
    uint32_t off = (uint32_t)(k & 31) * 272 + (n0 & 127) * 2;
    *reinterpret_cast<uint4*>(hi + tile + off) = make_uint4(h[0], h[1], h[2], h[3]);
    *reinterpret_cast<uint4*>(lo + tile + off) = make_uint4(l[0], l[1], l[2], l[3]);
}

// ---------------- split-bf16 mma.sync GEMM ----------------
// C[128,128] per block = sum over K of A x B (3-term split).
// modes: 0 A-layout split out (mblk = z*MZ + by)
//        1 pk^T: transposed A-layout out per batch, mask+swish
//        2 pv:  B-layout out per batch, mask
//        3 kv:  B-layout out, batch=z
//        4 final f32 out
__global__ void __launch_bounds__(256, 1)
gemm_mma(const char* __restrict__ Ah, const char* __restrict__ Al,
         const char* __restrict__ Bh, const char* __restrict__ Bl,
         int kch, long long sA, long long sB,
         int mode, char* __restrict__ outH, char* __restrict__ outL,
         float* __restrict__ outF, int MZ, const float* __restrict__ mask) {
    extern __shared__ __align__(1024) char smem[];
    uint32_t sb = s2u(smem);
    uint32_t st0 = sb + 1024;

    const int tid = threadIdx.x, lane = tid & 31, wid = tid >> 5;
    const int wm = wid >> 2, wn = wid & 3;
    const int bx = blockIdx.x, by = blockIdx.y, z = blockIdx.z;
    const int m0 = by * 128, n0 = bx * 128;
    const int g = lane >> 2, tg = lane & 3;

    if (tid == 0) {
        for (int s = 0; s < STAGES; ++s) MBARRIER_INIT(sb + 8 * s, 1);
    }
    __syncthreads();

    const char* Abh = Ah + (size_t)z * sA + (size_t)by * kch * TA;
    const char* Abl = Al + (size_t)z * sA + (size_t)by * kch * TA;
    const char* Bbh = Bh + (size_t)z * sB + (size_t)bx * kch * TBB;
    const char* Bbl = Bl + (size_t)z * sB + (size_t)bx * kch * TBB;

    if (tid == 0) {
        int np = STAGES < kch ? STAGES : kch;
        for (int s = 0; s < np; ++s) {
            MBARRIER_EXPECT_TX(sb + 8 * s, STG);
            uint32_t d = st0 + s * STG;
            bulk_g2s(d,            Abh + (size_t)s * TA,  TA,  sb + 8 * s);
            bulk_g2s(d + TA,       Abl + (size_t)s * TA,  TA,  sb + 8 * s);
            bulk_g2s(d + 2 * TA,   Bbh + (size_t)s * TBB, TBB, sb + 8 * s);
            bulk_g2s(d + 2*TA+TBB, Bbl + (size_t)s * TBB, TBB, sb + 8 * s);
        }
    }

    float acc[4][4][4];
#pragma unroll
    for (int i = 0; i < 4; i++)
#pragma unroll
        for (int j = 0; j < 4; j++)
#pragma unroll
            for (int r = 0; r < 4; r++) acc[i][j][r] = 0.0f;

    const uint32_t arow = (uint32_t)wm * 5120 + (uint32_t)(lane & 15) * 80 + (uint32_t)(lane >> 4) * 16;
    const uint32_t brow = (uint32_t)(lane & 15) * 272 + (uint32_t)wn * 64 + (uint32_t)(lane >> 4) * 16;

    for (int c = 0; c < kch; ++c) {
        int s = c % STAGES;
        int pf = (c / STAGES) & 1;
        MBARRIER_WAIT_PARITY(sb + 8 * s, pf);
        uint32_t sa = st0 + s * STG;
#pragma unroll
        for (int k16 = 0; k16 < 2; ++k16) {
            uint32_t ab = sa + arow + k16 * 32;
            uint32_t ah[4][4], al4[4][4];
#pragma unroll
            for (int mf = 0; mf < 4; ++mf) {
                ldsm4(ah[mf], ab + mf * 1280);
                ldsm4(al4[mf], ab + TA + mf * 1280);
            }
            uint32_t bb = sa + 2 * TA + brow + k16 * 4352;
            uint32_t bh[4][2], bl4[4][2], t[4];
            ldsm4t(t, bb);           bh[0][0]=t[0]; bh[0][1]=t[1]; bh[1][0]=t[2]; bh[1][1]=t[3];
            ldsm4t(t, bb + 32);      bh[2][0]=t[0]; bh[2][1]=t[1]; bh[3][0]=t[2]; bh[3][1]=t[3];
            ldsm4t(t, bb + TBB);     bl4[0][0]=t[0]; bl4[0][1]=t[1]; bl4[1][0]=t[2]; bl4[1][1]=t[3];
            ldsm4t(t, bb + TBB + 32);bl4[2][0]=t[0]; bl4[2][1]=t[1]; bl4[3][0]=t[2]; bl4[3][1]=t[3];
#pragma unroll
            for (int mf = 0; mf < 4; ++mf)
#pragma unroll
                for (int nf = 0; nf < 4; ++nf) {
                    mma16816(acc[mf][nf], ah[mf], bh[nf]);
                    mma16816(acc[mf][nf], al4[mf], bh[nf]);
                    mma16816(acc[mf][nf], ah[mf], bl4[nf]);
                }
        }
        __syncthreads();
        if (tid == 0 && c + STAGES < kch) {
            int cn = c + STAGES;
            MBARRIER_EXPECT_TX(sb + 8 * s, STG);
            uint32_t d = st0 + s * STG;
            bulk_g2s(d,            Abh + (size_t)cn * TA,  TA,  sb + 8 * s);
            bulk_g2s(d + TA,       Abl + (size_t)cn * TA,  TA,  sb + 8 * s);
            bulk_g2s(d + 2 * TA,   Bbh + (size_t)cn * TBB, TBB, sb + 8 * s);
            bulk_g2s(d + 2*TA+TBB, Bbl + (size_t)cn * TBB, TBB, sb + 8 * s);
        }
    }

    // ---------------- epilogue ----------------
    if (mode == 4) {
#pragma unroll
        for (int mf = 0; mf < 4; ++mf)
#pragma unroll
            for (int nf = 0; nf < 4; ++nf)
#pragma unroll
                for (int rh = 0; rh < 2; ++rh) {
                    int row = wm * 64 + mf * 16 + g + rh * 8;
                    int gcol = n0 + wn * 32 + nf * 8 + tg * 2;
                    float2 v = make_float2(acc[mf][nf][rh * 2], acc[mf][nf][rh * 2 + 1]);
                    *reinterpret_cast<float2*>(outF + (size_t)(m0 + row) * 1024 + gcol) = v;
                }
    } else if (mode == 0) {
        size_t mtile = ((size_t)(z * MZ + by) * 32 + bx * 4 + wn) * TA;
#pragma unroll
        for (int mf = 0; mf < 4; ++mf)
#pragma unroll
            for (int nf = 0; nf < 4; ++nf)
#pragma unroll
                for (int rh = 0; rh < 2; ++rh) {
                    int row = wm * 64 + mf * 16 + g + rh * 8;
                    uint32_t hw, lw;
                    split2(acc[mf][nf][rh * 2], acc[mf][nf][rh * 2 + 1], hw, lw);
                    uint32_t off = (uint32_t)row * 80 + (nf * 8 + tg * 2) * 2;
                    *reinterpret_cast<uint32_t*>(outH + mtile + off) = hw;
                    *reinterpret_cast<uint32_t*>(outL + mtile + off) = lw;
                }
    } else if (mode == 2 || mode == 3) {
        int bt = (mode == 2) ? (by >> 5) : z;
        int kbase = (mode == 2) ? (m0 & 4095) : m0;
        int tilescale = (mode == 2) ? 128 : 32;
#pragma unroll
        for (int mf = 0; mf < 4; ++mf)
#pragma unroll
            for (int rh = 0; rh < 2; ++rh) {
                int row = wm * 64 + mf * 16 + g + rh * 8;
                float mv = (mode == 2) ? mask[m0 + row] : 1.0f;
                int kloc = kbase + row;
                size_t tile = ((size_t)(bt * 8 + bx) * tilescale + (kloc >> 5)) * TBB;
                uint32_t rowoff = (uint32_t)(kloc & 31) * 272;
#pragma unroll
                for (int nf = 0; nf < 4; ++nf) {
                    uint32_t hw, lw;
                    split2(acc[mf][nf][rh * 2] * mv, acc[mf][nf][rh * 2 + 1] * mv, hw, lw);
                    uint32_t off = rowoff + (wn * 32 + nf * 8 + tg * 2) * 2;
                    *reinterpret_cast<uint32_t*>(outH + tile + off) = hw;
                    *reinterpret_cast<uint32_t*>(outL + tile + off) = lw;
                }
            }
    } else {
        // mode 1: mask + swish, store transposed A-layout via smem staging
        uint32_t shh = st0, sll = st0 + 34816;   // each [128][136] bf16 = 34816B
#pragma unroll
        for (int mf = 0; mf < 4; ++mf)
#pragma unroll
            for (int rh = 0; rh < 2; ++rh) {
                int row = wm * 64 + mf * 16 + g + rh * 8;
                float mv = mask[m0 + row];
#pragma unroll
                for (int nf = 0; nf < 4; ++nf) {
                    float v0 = acc[mf][nf][rh * 2] * mv;
                    float v1 = acc[mf][nf][rh * 2 + 1] * mv;
                    v0 = v0 / (1.0f + expf(-v0));
                    v1 = v1 / (1.0f + expf(-v1));
                    uint32_t hw, lw;
                    split2(v0, v1, hw, lw);
                    uint32_t a = (uint32_t)row * 272 + (wn * 32 + nf * 8 + tg * 2) * 2;
                    asm volatile("st.shared.b32 [%0], %1;" :: "r"(shh + a), "r"(hw) : "memory");
                    asm volatile("st.shared.b32 [%0], %1;" :: "r"(sll + a), "r"(lw) : "memory");
                }
            }
        __syncthreads();
        int u = tid & 127;
        int sh2 = (tid >> 7) * 64;
        int bt = by >> 5;
        int kc0 = (m0 & 4095) >> 5;
#pragma unroll
        for (int c8 = 0; c8 < 8; ++c8) {
            int s0 = sh2 + c8 * 8;
            uint32_t hw[4], lw[4];
#pragma unroll
            for (int p = 0; p < 4; ++p) {
                unsigned short h0, h1, l0, l1;
                uint32_t a0 = (uint32_t)(s0 + 2 * p) * 272 + (uint32_t)u * 2;
                uint32_t a1 = a0 + 272;
                asm volatile("ld.shared.b16 %0, [%1];" : "=h"(h0) : "r"(shh + a0));
                asm volatile("ld.shared.b16 %0, [%1];" : "=h"(h1) : "r"(shh + a1));
                asm volatile("ld.shared.b16 %0, [%1];" : "=h"(l0) : "r"(sll + a0));
                asm volatile("ld.shared.b16 %0, [%1];" : "=h"(l1) : "r"(sll + a1));
                hw[p] = (uint32_t)h0 | ((uint32_t)h1 << 16);
                lw[p] = (uint32_t)l0 | ((uint32_t)l1 << 16);
            }
            size_t tile = ((size_t)(bt * 8 + bx) * 128 + kc0 + (s0 >> 5)) * TA;
            uint32_t off = (uint32_t)u * 80 + (s0 & 31) * 2;
            *reinterpret_cast<uint4*>(outH + tile + off) = make_uint4(hw[0], hw[1], hw[2], hw[3]);
            *reinterpret_cast<uint4*>(outL + tile + off) = make_uint4(lw[0], lw[1], lw[2], lw[3]);
        }
    }
}

// ---------------- launch ----------------
extern "C" void kernel_launch(void* const* d_in, const int* in_sizes, int n_in,
                              void* d_out, int out_size) {
    const float* query = (const float*)d_in[0];
    const float* key   = (const float*)d_in[1];
    const float* value = (const float*)d_in[2];
    const float* mask  = (const float*)d_in[3];
    const float* Wk    = (const float*)d_in[4];
    const float* Wv    = (const float*)d_in[5];
    const float* Wq    = (const float*)d_in[6];
    const float* Wo    = (const float*)d_in[7];
    float* out = (float*)d_out;

    char *qh,*ql,*kh,*kl,*vh,*vl,*wqh,*wql,*wkh,*wkl,*wvh,*wvl,*woh,*wol;
    char *pqh,*pql,*o1h,*o1l,*pkth,*pktl,*pvh,*pvl,*kvh,*kvl;
    cudaGetSymbolAddress((void**)&qh, g_qh);   cudaGetSymbolAddress((void**)&ql, g_ql);
    cudaGetSymbolAddress((void**)&kh, g_kh);   cudaGetSymbolAddress((void**)&kl, g_kl);
    cudaGetSymbolAddress((void**)&vh, g_vh);   cudaGetSymbolAddress((void**)&vl, g_vl);
    cudaGetSymbolAddress((void**)&wqh, g_wqh); cudaGetSymbolAddress((void**)&wql, g_wql);
    cudaGetSymbolAddress((void**)&wkh, g_wkh); cudaGetSymbolAddress((void**)&wkl, g_wkl);
    cudaGetSymbolAddress((void**)&wvh, g_wvh); cudaGetSymbolAddress((void**)&wvl, g_wvl);
    cudaGetSymbolAddress((void**)&woh, g_woh); cudaGetSymbolAddress((void**)&wol, g_wol);
    cudaGetSymbolAddress((void**)&pqh, g_pqh); cudaGetSymbolAddress((void**)&pql, g_pql);
    cudaGetSymbolAddress((void**)&o1h, g_o1h); cudaGetSymbolAddress((void**)&o1l, g_o1l);
    cudaGetSymbolAddress((void**)&pkth, g_pkth); cudaGetSymbolAddress((void**)&pktl, g_pktl);
    cudaGetSymbolAddress((void**)&pvh, g_pvh); cudaGetSymbolAddress((void**)&pvl, g_pvl);
    cudaGetSymbolAddress((void**)&kvh, g_kvh); cudaGetSymbolAddress((void**)&kvl, g_kvl);

    cudaFuncSetAttribute(gemm_mma, cudaFuncAttributeMaxDynamicSharedMemorySize, SMEM_SZ);

    conv_act<<<8192, 256>>>(query, qh, ql);
    conv_act<<<8192, 256>>>(key,   kh, kl);
    conv_act<<<8192, 256>>>(value, vh, vl);
    conv_w<<<512, 256>>>(Wq, wqh, wql);
    conv_w<<<512, 256>>>(Wk, wkh, wkl);
    conv_w<<<512, 256>>>(Wv, wvh, wvl);
    conv_w<<<512, 256>>>(Wo, woh, wol);

    dim3 blk(256);
    // pq = q @ Wq        -> A-layout out
    gemm_mma<<<dim3(8,128,1), blk, SMEM_SZ>>>(qh, ql, wqh, wql, 32, 0, 0,
        0, pqh, pql, nullptr, 0, nullptr);
    // pk^T = swish(mask*(k @ Wk)) transposed per batch
    gemm_mma<<<dim3(8,128,1), blk, SMEM_SZ>>>(kh, kl, wkh, wkl, 32, 0, 0,
        1, pkth, pktl, nullptr, 0, mask);
    // pv = mask*(v @ Wv) -> B-layout per batch
    gemm_mma<<<dim3(8,128,1), blk, SMEM_SZ>>>(vh, vl, wvh, wvl, 32, 0, 0,
        2, pvh, pvl, nullptr, 0, mask);
    // kv[b] = pk^T @ pv  (M=1024, N=1024, K=4096) -> B-layout
    gemm_mma<<<dim3(8,8,4), blk, SMEM_SZ>>>(pkth, pktl, pvh, pvl, 128,
        (long long)8*128*TA, (long long)8*128*TBB,
        3, kvh, kvl, nullptr, 0, nullptr);
    // o1[b] = pq[b] @ kv[b] (M=4096, N=1024, K=1024) -> A-layout out
    gemm_mma<<<dim3(8,32,4), blk, SMEM_SZ>>>(pqh, pql, kvh, kvl, 32,
        (long long)32*32*TA, (long long)8*32*TBB,
        0, o1h, o1l, nullptr, 32, nullptr);
    // out = o1 @ Wo -> f32
    gemm_mma<<<dim3(8,128,1), blk, SMEM_SZ>>>(o1h, o1l, woh, wol, 32, 0, 0,
        4, nullptr, nullptr, out, 0, nullptr);
}

// round 5
// speedup vs baseline: 2.7704x; 1.0268x over previous
#include <cuda_runtime.h>
#include <cuda_bf16.h>
#include <cstdint>
#include <string.h>
#include <math.h>

typedef __nv_bfloat16 bf16;

// Tile geometry: A tiles [128 rows][40 cols pad (32 real)] bf16 ; B tiles [32 rows][136 cols pad (128 real)]
#define TA 10240
#define TBB 8704
#define STG (2*TA + 2*TBB)     // 37888 per stage (Ah, Al, Bh, Bl)
#define STAGES 4
#define SMEM_SZ (1024 + STAGES*STG)

// ---------------- device-global scratch ----------------
__device__ __align__(128) char g_qh[128*32*TA], g_ql[128*32*TA];
__device__ __align__(128) char g_kh[128*32*TA], g_kl[128*32*TA];
__device__ __align__(128) char g_vh[128*32*TA], g_vl[128*32*TA];
__device__ __align__(128) char g_wqh[8*32*TBB], g_wql[8*32*TBB];
__device__ __align__(128) char g_wkh[8*32*TBB], g_wkl[8*32*TBB];
__device__ __align__(128) char g_wvh[8*32*TBB], g_wvl[8*32*TBB];
__device__ __align__(128) char g_woh[8*32*TBB], g_wol[8*32*TBB];
__device__ __align__(128) char g_pqh[128*32*TA], g_pql[128*32*TA];
__device__ __align__(128) char g_o1h[128*32*TA], g_o1l[128*32*TA];
__device__ __align__(128) char g_pkth[4*8*128*TA], g_pktl[4*8*128*TA];   // pk^T A-layout per batch
__device__ __align__(128) char g_pvh[4*8*128*TBB], g_pvl[4*8*128*TBB];   // pv B-layout per batch
__device__ __align__(128) char g_kvh[4*8*32*TBB], g_kvl[4*8*32*TBB];     // kv B-layout per batch

// ---------------- PTX helpers ----------------
__device__ __forceinline__ uint32_t s2u(const void* p) {
    uint32_t a;
    asm("{ .reg .u64 t; cvta.to.shared.u64 t, %1; cvt.u32.u64 %0, t; }" : "=r"(a) : "l"(p));
    return a;
}
#define MBARRIER_INIT(addr, cnt) \
    asm volatile("mbarrier.init.shared.b64 [%0], %1;" :: "r"((uint32_t)(addr)), "r"((uint32_t)(cnt)) : "memory")
#define MBARRIER_EXPECT_TX(addr, bytes) \
    asm volatile("mbarrier.arrive.expect_tx.shared.b64 _, [%0], %1;" :: "r"((uint32_t)(addr)), "r"((uint32_t)(bytes)) : "memory")
#define MBARRIER_WAIT_PARITY(mbar, par) do { \
    uint32_t _m = (uint32_t)(mbar); uint32_t _p = (uint32_t)(par); uint32_t _d; \
    asm volatile("{\n\t.reg .pred p;\n\tmbarrier.try_wait.parity.acquire.cta.shared::cta.b64 p, [%1], %2;\n\tselp.b32 %0, 1, 0, p;\n\t}" \
        : "=r"(_d) : "r"(_m), "r"(_p) : "memory"); \
    if (!_d) { \
        asm volatile("{\n\t.reg .pred P1;\n\tWL_%=:\n\tmbarrier.try_wait.parity.acquire.cta.shared::cta.b64 P1, [%0], %1, 0x989680;\n\t@P1 bra.uni WD_%=;\n\tbra.uni WL_%=;\n\tWD_%=:\n\t}" \
            :: "r"(_m), "r"(_p) : "memory"); \
    } \
} while(0)

__device__ __forceinline__ void bulk_g2s(uint32_t dst, const void* src, uint32_t bytes, uint32_t mbar) {
    asm volatile("cp.async.bulk.shared::cluster.global.mbarrier::complete_tx::bytes [%0], [%1], %2, [%3];"
        :: "r"(dst), "l"(src), "r"(bytes), "r"(mbar) : "memory");
}
__device__ __forceinline__ void ldsm4(uint32_t* r, uint32_t a) {
    asm volatile("ldmatrix.sync.aligned.m8n8.x4.shared.b16 {%0,%1,%2,%3}, [%4];"
        : "=r"(r[0]), "=r"(r[1]), "=r"(r[2]), "=r"(r[3]) : "r"(a));
}
__device__ __forceinline__ void ldsm4t(uint32_t* r, uint32_t a) {
    asm volatile("ldmatrix.sync.aligned.m8n8.x4.trans.shared.b16 {%0,%1,%2,%3}, [%4];"
        : "=r"(r[0]), "=r"(r[1]), "=r"(r[2]), "=r"(r[3]) : "r"(a));
}
__device__ __forceinline__ void mma16816(float* c, const uint32_t* a, const uint32_t* b) {
    asm volatile("mma.sync.aligned.m16n8k16.row.col.f32.bf16.bf16.f32 "
        "{%0,%1,%2,%3}, {%4,%5,%6,%7}, {%8,%9}, {%0,%1,%2,%3};"
        : "+f"(c[0]), "+f"(c[1]), "+f"(c[2]), "+f"(c[3])
        : "r"(a[0]), "r"(a[1]), "r"(a[2]), "r"(a[3]), "r"(b[0]), "r"(b[1]));
}

__device__ __forceinline__ unsigned short bfraw(bf16 h) { unsigned short u; memcpy(&u, &h, 2); return u; }
__device__ __forceinline__ void split2(float x, float y, uint32_t& H, uint32_t& L) {
    bf16 hx = __float2bfloat16(x), hy = __float2bfloat16(y);
    bf16 lx = __float2bfloat16(x - __bfloat162float(hx));
    bf16 ly = __float2bfloat16(y - __bfloat162float(hy));
    H = (uint32_t)bfraw(hx) | ((uint32_t)bfraw(hy) << 16);
    L = (uint32_t)bfraw(lx) | ((uint32_t)bfraw(ly) << 16);
}

// ---------------- conversions ----------------
// activations [M][1024] f32 -> A-layout tiles [mblk][kblk 0..31][128][40]
__global__ void conv_acts(const float* __restrict__ q, const float* __restrict__ k,
                          const float* __restrict__ v) {
    int zz = blockIdx.y;
    const float* src = zz == 0 ? q : zz == 1 ? k : v;
    char* hi = zz == 0 ? g_qh : zz == 1 ? g_kh : g_vh;
    char* lo = zz == 0 ? g_ql : zz == 1 ? g_kl : g_vl;
    int idx = blockIdx.x * 256 + threadIdx.x;   // M*128
    int m = idx >> 7;
    int k0 = (idx & 127) << 3;
    const float4* s = reinterpret_cast<const float4*>(src + ((size_t)m << 10) + k0);
    float4 a = s[0], b = s[1];
    uint32_t h[4], l[4];
    split2(a.x, a.y, h[0], l[0]); split2(a.z, a.w, h[1], l[1]);
    split2(b.x, b.y, h[2], l[2]); split2(b.z, b.w, h[3], l[3]);
    size_t tile = ((size_t)(m >> 7) * 32 + (k0 >> 5)) * TA;
    uint32_t off = (uint32_t)(m & 127) * 80 + (k0 & 31) * 2;
    *reinterpret_cast<uint4*>(hi + tile + off) = make_uint4(h[0], h[1], h[2], h[3]);
    *reinterpret_cast<uint4*>(lo + tile + off) = make_uint4(l[0], l[1], l[2], l[3]);
}
// W [1024 k][1024 n] f32 -> B-layout tiles [nblk][kblk][32][136]
__global__ void conv_ws(const float* __restrict__ Wq, const float* __restrict__ Wk,
                        const float* __restrict__ Wv, const float* __restrict__ Wo) {
    int zz = blockIdx.y;
    const float* W = zz == 0 ? Wq : zz == 1 ? Wk : zz == 2 ? Wv : Wo;
    char* hi = zz == 0 ? g_wqh : zz == 1 ? g_wkh : zz == 2 ? g_wvh : g_woh;
    char* lo = zz == 0 ? g_wql : zz == 1 ? g_wkl : zz == 2 ? g_wvl : g_wol;
    int idx = blockIdx.x * 256 + threadIdx.x;   // 1024*128
    int k = idx >> 7;
    int n0 = (idx & 127) << 3;
    const float4* s = reinterpret_cast<const float4*>(W + ((size_t)k << 10) + n0);
    float4 a = s[0], b = s[1];
    uint32_t h[4], l[4];
    split2(a.x, a.y, h[0], l[0]); split2(a.z, a.w, h[1], l[1]);
    split2(b.x, b.y, h[2], l[2]); split2(b.z, b.w, h[3], l[3]);
    size_t tile = ((size_t)(n0 >> 7) * 32 + (k >> 5)) * TBB;
    uint32_t off = (uint32_t)(k & 31) * 272 + (n0 & 127) * 2;
    *reinterpret_cast<uint4*>(hi + tile + off) = make_uint4(h[0], h[1], h[2], h[3]);
    *reinterpret_cast<uint4*>(lo + tile + off) = make_uint4(l[0], l[1], l[2], l[3]);
}

// ---------------- shared GEMM mainloop ----------------
__device__ __forceinline__ void refill(uint32_t st0, uint32_t sb, int s,
        const char* Abh, const char* Abl, const char* Bbh, const char* Bbl, int c) {
    MBARRIER_EXPECT_TX(sb + 8 * s, STG);
    uint32_t d = st0 + s * STG;
    bulk_g2s(d,            Abh + (size_t)c * TA,  TA,  sb + 8 * s);
    bulk_g2s(d + TA,       Abl + (size_t)c * TA,  TA,  sb + 8 * s);
    bulk_g2s(d + 2 * TA,   Bbh + (size_t)c * TBB, TBB, sb + 8 * s);
    bulk_g2s(d + 2*TA+TBB, Bbl + (size_t)c * TBB, TBB, sb + 8 * s);
}

__device__ __forceinline__ void gemm_core(
        const char* __restrict__ Abh, const char* __restrict__ Abl,
        const char* __restrict__ Bbh, const char* __restrict__ Bbl,
        int kch, uint32_t sb, uint32_t st0, float acc[4][4][4]) {
    const int tid = threadIdx.x, lane = tid & 31, wid = tid >> 5;
    const int wm = wid >> 2, wn = wid & 3;

    if (tid == 0)
        for (int s = 0; s < STAGES; ++s) MBARRIER_INIT(sb + 8 * s, 1);
    __syncthreads();

    if (tid == 0) {
        int np = STAGES < kch ? STAGES : kch;
        for (int s = 0; s < np; ++s) refill(st0, sb, s, Abh, Abl, Bbh, Bbl, s);
    }

#pragma unroll
    for (int i = 0; i < 4; i++)
#pragma unroll
        for (int j = 0; j < 4; j++)
#pragma unroll
            for (int r = 0; r < 4; r++) acc[i][j][r] = 0.0f;

    const uint32_t arow = (uint32_t)wm * 5120 + (uint32_t)(lane & 15) * 80 + (uint32_t)(lane >> 4) * 16;
    const uint32_t brow = (uint32_t)(lane & 15) * 272 + (uint32_t)wn * 64 + (uint32_t)(lane >> 4) * 16;

    for (int c = 0; c < kch; ++c) {
        int s = c % STAGES;
        int pf = (c / STAGES) & 1;
        MBARRIER_WAIT_PARITY(sb + 8 * s, pf);
        uint32_t sa = st0 + s * STG;
#pragma unroll
        for (int k16 = 0; k16 < 2; ++k16) {
            uint32_t ab = sa + arow + k16 * 32;
            uint32_t ah[4][4], al4[4][4];
#pragma unroll
            for (int mf = 0; mf < 4; ++mf) {
                ldsm4(ah[mf], ab + mf * 1280);
                ldsm4(al4[mf], ab + TA + mf * 1280);
            }
            uint32_t bb = sa + 2 * TA + brow + k16 * 4352;
            uint32_t bh[4][2], bl4[4][2], t[4];
            ldsm4t(t, bb);            bh[0][0]=t[0]; bh[0][1]=t[1]; bh[1][0]=t[2]; bh[1][1]=t[3];
            ldsm4t(t, bb + 32);       bh[2][0]=t[0]; bh[2][1]=t[1]; bh[3][0]=t[2]; bh[3][1]=t[3];
            ldsm4t(t, bb + TBB);      bl4[0][0]=t[0]; bl4[0][1]=t[1]; bl4[1][0]=t[2]; bl4[1][1]=t[3];
            ldsm4t(t, bb + TBB + 32); bl4[2][0]=t[0]; bl4[2][1]=t[1]; bl4[3][0]=t[2]; bl4[3][1]=t[3];
#pragma unroll
            for (int mf = 0; mf < 4; ++mf)
#pragma unroll
                for (int nf = 0; nf < 4; ++nf) {
                    mma16816(acc[mf][nf], ah[mf], bh[nf]);
                    mma16816(acc[mf][nf], al4[mf], bh[nf]);
                    mma16816(acc[mf][nf], ah[mf], bl4[nf]);
                }
        }
        __syncthreads();
        if (tid == 0 && c + STAGES < kch)
            refill(st0, sb, s, Abh, Abl, Bbh, Bbl, c + STAGES);
    }
}

// ---------------- GEMM kernels ----------------
// Projections: z=0 q->pq (A-layout), z=1 k->pkT (mask+swish, transposed), z=2 v->pv (mask, B-layout)
__global__ void __launch_bounds__(256, 1)
proj_gemm(const float* __restrict__ mask) {
    extern __shared__ __align__(1024) char smem[];
    uint32_t sb = s2u(smem), st0 = sb + 1024;
    const int tid = threadIdx.x, lane = tid & 31, wid = tid >> 5;
    const int wm = wid >> 2, wn = wid & 3;
    const int bx = blockIdx.x, by = blockIdx.y, z = blockIdx.z;
    const int m0 = by * 128;
    const int g = lane >> 2, tg = lane & 3;

    const char* Ah = z == 0 ? g_qh : z == 1 ? g_kh : g_vh;
    const char* Al = z == 0 ? g_ql : z == 1 ? g_kl : g_vl;
    const char* Bh = z == 0 ? g_wqh : z == 1 ? g_wkh : g_wvh;
    const char* Bl = z == 0 ? g_wql : z == 1 ? g_wkl : g_wvl;

    float acc[4][4][4];
    gemm_core(Ah + (size_t)by * 32 * TA, Al + (size_t)by * 32 * TA,
              Bh + (size_t)bx * 32 * TBB, Bl + (size_t)bx * 32 * TBB,
              32, sb, st0, acc);

    if (z == 0) {
        // pq: A-layout out
        size_t mtile = ((size_t)by * 32 + bx * 4 + wn) * TA;
#pragma unroll
        for (int mf = 0; mf < 4; ++mf)
#pragma unroll
            for (int nf = 0; nf < 4; ++nf)
#pragma unroll
                for (int rh = 0; rh < 2; ++rh) {
                    int row = wm * 64 + mf * 16 + g + rh * 8;
                    uint32_t hw, lw;
                    split2(acc[mf][nf][rh * 2], acc[mf][nf][rh * 2 + 1], hw, lw);
                    uint32_t off = (uint32_t)row * 80 + (nf * 8 + tg * 2) * 2;
                    *reinterpret_cast<uint32_t*>(g_pqh + mtile + off) = hw;
                    *reinterpret_cast<uint32_t*>(g_pql + mtile + off) = lw;
                }
    } else if (z == 2) {
        // pv: mask, B-layout per batch
        int bt = by >> 5;
#pragma unroll
        for (int mf = 0; mf < 4; ++mf)
#pragma unroll
            for (int rh = 0; rh < 2; ++rh) {
                int row = wm * 64 + mf * 16 + g + rh * 8;
                float mv = mask[m0 + row];
                int kloc = (m0 & 4095) + row;
                size_t tile = ((size_t)(bt * 8 + bx) * 128 + (kloc >> 5)) * TBB;
                uint32_t rowoff = (uint32_t)(kloc & 31) * 272;
#pragma unroll
                for (int nf = 0; nf < 4; ++nf) {
                    uint32_t hw, lw;
                    split2(acc[mf][nf][rh * 2] * mv, acc[mf][nf][rh * 2 + 1] * mv, hw, lw);
                    uint32_t off = rowoff + (wn * 32 + nf * 8 + tg * 2) * 2;
                    *reinterpret_cast<uint32_t*>(g_pvh + tile + off) = hw;
                    *reinterpret_cast<uint32_t*>(g_pvl + tile + off) = lw;
                }
            }
    } else {
        // pk^T: mask + swish, transposed A-layout via smem staging
        uint32_t shh = st0, sll = st0 + 34816;
#pragma unroll
        for (int mf = 0; mf < 4; ++mf)
#pragma unroll
            for (int rh = 0; rh < 2; ++rh) {
                int row = wm * 64 + mf * 16 + g + rh * 8;
                float mv = mask[m0 + row];
#pragma unroll
                for (int nf = 0; nf < 4; ++nf) {
                    float v0 = acc[mf][nf][rh * 2] * mv;
                    float v1 = acc[mf][nf][rh * 2 + 1] * mv;
                    v0 = v0 / (1.0f + __expf(-v0));
                    v1 = v1 / (1.0f + __expf(-v1));
                    uint32_t hw, lw;
                    split2(v0, v1, hw, lw);
                    uint32_t a = (uint32_t)row * 272 + (wn * 32 + nf * 8 + tg * 2) * 2;
                    asm volatile("st.shared.b32 [%0], %1;" :: "r"(shh + a), "r"(hw) : "memory");
                    asm volatile("st.shared.b32 [%0], %1;" :: "r"(sll + a), "r"(lw) : "memory");
                }
            }
        __syncthreads();
        int u = tid & 127;
        int sh2 = (tid >> 7) * 64;
        int bt = by >> 5;
        int kc0 = (m0 & 4095) >> 5;
#pragma unroll
        for (int c8 = 0; c8 < 8; ++c8) {
            int s0 = sh2 + c8 * 8;
            uint32_t hw[4], lw[4];
#pragma unroll
            for (int p = 0; p < 4; ++p) {
                unsigned short h0, h1, l0, l1;
                uint32_t a0 = (uint32_t)(s0 + 2 * p) * 272 + (uint32_t)u * 2;
                uint32_t a1 = a0 + 272;
                asm volatile("ld.shared.b16 %0, [%1];" : "=h"(h0) : "r"(shh + a0));
                asm volatile("ld.shared.b16 %0, [%1];" : "=h"(h1) : "r"(shh + a1));
                asm volatile("ld.shared.b16 %0, [%1];" : "=h"(l0) : "r"(sll + a0));
                asm volatile("ld.shared.b16 %0, [%1];" : "=h"(l1) : "r"(sll + a1));
                hw[p] = (uint32_t)h0 | ((uint32_t)h1 << 16);
                lw[p] = (uint32_t)l0 | ((uint32_t)l1 << 16);
            }
            size_t tile = ((size_t)(bt * 8 + bx) * 128 + kc0 + (s0 >> 5)) * TA;
            uint32_t off = (uint32_t)u * 80 + (s0 & 31) * 2;
            *reinterpret_cast<uint4*>(g_pkth + tile + off) = make_uint4(hw[0], hw[1], hw[2], hw[3]);
            *reinterpret_cast<uint4*>(g_pktl + tile + off) = make_uint4(lw[0], lw[1], lw[2], lw[3]);
        }
    }
}

// kv[b] = pk^T @ pv  (M=1024, N=1024, K=4096) -> B-layout
__global__ void __launch_bounds__(256, 1)
kv_gemm() {
    extern __shared__ __align__(1024) char smem[];
    uint32_t sb = s2u(smem), st0 = sb + 1024;
    const int tid = threadIdx.x, lane = tid & 31, wid = tid >> 5;
    const int wm = wid >> 2, wn = wid & 3;
    const int bx = blockIdx.x, by = blockIdx.y, z = blockIdx.z;
    const int m0 = by * 128;
    const int g = lane >> 2, tg = lane & 3;

    float acc[4][4][4];
    gemm_core(g_pkth + (size_t)(z * 8 + by) * 128 * TA, g_pktl + (size_t)(z * 8 + by) * 128 * TA,
              g_pvh + (size_t)(z * 8 + bx) * 128 * TBB, g_pvl + (size_t)(z * 8 + bx) * 128 * TBB,
              128, sb, st0, acc);

#pragma unroll
    for (int mf = 0; mf < 4; ++mf)
#pragma unroll
        for (int rh = 0; rh < 2; ++rh) {
            int row = wm * 64 + mf * 16 + g + rh * 8;
            int kloc = m0 + row;
            size_t tile = ((size_t)(z * 8 + bx) * 32 + (kloc >> 5)) * TBB;
            uint32_t rowoff = (uint32_t)(kloc & 31) * 272;
#pragma unroll
            for (int nf = 0; nf < 4; ++nf) {
                uint32_t hw, lw;
                split2(acc[mf][nf][rh * 2], acc[mf][nf][rh * 2 + 1], hw, lw);
                uint32_t off = rowoff + (wn * 32 + nf * 8 + tg * 2) * 2;
                *reinterpret_cast<uint32_t*>(g_kvh + tile + off) = hw;
                *reinterpret_cast<uint32_t*>(g_kvl + tile + off) = lw;
            }
        }
}

// o1[b] = pq[b] @ kv[b] (M=4096, N=1024, K=1024) -> A-layout
__global__ void __launch_bounds__(256, 1)
o1_gemm() {
    extern __shared__ __align__(1024) char smem[];
    uint32_t sb = s2u(smem), st0 = sb + 1024;
    const int tid = threadIdx.x, lane = tid & 31, wid = tid >> 5;
    const int wm = wid >> 2, wn = wid & 3;
    const int bx = blockIdx.x, by = blockIdx.y, z = blockIdx.z;
    const int g = lane >> 2, tg = lane & 3;
    const int mb = z * 32 + by;

    float acc[4][4][4];
    gemm_core(g_pqh + (size_t)mb * 32 * TA, g_pql + (size_t)mb * 32 * TA,
              g_kvh + (size_t)(z * 8 + bx) * 32 * TBB, g_kvl + (size_t)(z * 8 + bx) * 32 * TBB,
              32, sb, st0, acc);

    size_t mtile = ((size_t)mb * 32 + bx * 4 + wn) * TA;
#pragma unroll
    for (int mf = 0; mf < 4; ++mf)
#pragma unroll
        for (int nf = 0; nf < 4; ++nf)
#pragma unroll
            for (int rh = 0; rh < 2; ++rh) {
                int row = wm * 64 + mf * 16 + g + rh * 8;
                uint32_t hw, lw;
                split2(acc[mf][nf][rh * 2], acc[mf][nf][rh * 2 + 1], hw, lw);
                uint32_t off = (uint32_t)row * 80 + (nf * 8 + tg * 2) * 2;
                *reinterpret_cast<uint32_t*>(g_o1h + mtile + off) = hw;
                *reinterpret_cast<uint32_t*>(g_o1l + mtile + off) = lw;
            }
}

// out = o1 @ Wo -> f32
__global__ void __launch_bounds__(256, 1)
wo_gemm(float* __restrict__ outF) {
    extern __shared__ __align__(1024) char smem[];
    uint32_t sb = s2u(smem), st0 = sb + 1024;
    const int tid = threadIdx.x, lane = tid & 31, wid = tid >> 5;
    const int wm = wid >> 2, wn = wid & 3;
    const int bx = blockIdx.x, by = blockIdx.y;
    const int m0 = by * 128, n0 = bx * 128;
    const int g = lane >> 2, tg = lane & 3;

    float acc[4][4][4];
    gemm_core(g_o1h + (size_t)by * 32 * TA, g_o1l + (size_t)by * 32 * TA,
              g_woh + (size_t)bx * 32 * TBB, g_wol + (size_t)bx * 32 * TBB,
              32, sb, st0, acc);

#pragma unroll
    for (int mf = 0; mf < 4; ++mf)
#pragma unroll
        for (int nf = 0; nf < 4; ++nf)
#pragma unroll
            for (int rh = 0; rh < 2; ++rh) {
                int row = wm * 64 + mf * 16 + g + rh * 8;
                int gcol = n0 + wn * 32 + nf * 8 + tg * 2;
                float2 v = make_float2(acc[mf][nf][rh * 2], acc[mf][nf][rh * 2 + 1]);
                *reinterpret_cast<float2*>(outF + (size_t)(m0 + row) * 1024 + gcol) = v;
            }
}

// ---------------- launch ----------------
extern "C" void kernel_launch(void* const* d_in, const int* in_sizes, int n_in,
                              void* d_out, int out_size) {
    const float* query = (const float*)d_in[0];
    const float* key   = (const float*)d_in[1];
    const float* value = (const float*)d_in[2];
    const float* mask  = (const float*)d_in[3];
    const float* Wk    = (const float*)d_in[4];
    const float* Wv    = (const float*)d_in[5];
    const float* Wq    = (const float*)d_in[6];
    const float* Wo    = (const float*)d_in[7];
    float* out = (float*)d_out;

    static bool attr_done = false;
    if (!attr_done) {
        cudaFuncSetAttribute(proj_gemm, cudaFuncAttributeMaxDynamicSharedMemorySize, SMEM_SZ);
        cudaFuncSetAttribute(kv_gemm,   cudaFuncAttributeMaxDynamicSharedMemorySize, SMEM_SZ);
        cudaFuncSetAttribute(o1_gemm,   cudaFuncAttributeMaxDynamicSharedMemorySize, SMEM_SZ);
        cudaFuncSetAttribute(wo_gemm,   cudaFuncAttributeMaxDynamicSharedMemorySize, SMEM_SZ);
        attr_done = true;
    }

    conv_acts<<<dim3(8192, 3), 256>>>(query, key, value);
    conv_ws<<<dim3(512, 4), 256>>>(Wq, Wk, Wv, Wo);

    proj_gemm<<<dim3(8, 128, 3), 256, SMEM_SZ>>>(mask);
    kv_gemm<<<dim3(8, 8, 4), 256, SMEM_SZ>>>();
    o1_gemm<<<dim3(8, 32, 4), 256, SMEM_SZ>>>();
    wo_gemm<<<dim3(8, 128, 1), 256, SMEM_SZ>>>(out);
}

// round 6
// speedup vs baseline: 3.2538x; 1.1745x over previous
#include <cuda_runtime.h>
#include <cuda_bf16.h>
#include <cstdint>
#include <string.h>
#include <math.h>

typedef __nv_bfloat16 bf16;

// Tile geometry: A tiles [128 rows][40 cols pad (32 real)] bf16 ; B tiles [32 rows][136 cols pad (128 real)]
#define TA 10240
#define TBB 8704
#define STG (2*TA + 2*TBB)     // 37888 per stage (Ah, Al, Bh, Bl)
#define STAGES 2
#define SMEM_SZ (1024 + STAGES*STG)   // 76800 -> 2 CTAs/SM

// ---------------- device-global scratch ----------------
__device__ __align__(128) char g_qh[128*32*TA], g_ql[128*32*TA];
__device__ __align__(128) char g_kh[128*32*TA], g_kl[128*32*TA];
__device__ __align__(128) char g_vh[128*32*TA], g_vl[128*32*TA];
__device__ __align__(128) char g_wqh[8*32*TBB], g_wql[8*32*TBB];
__device__ __align__(128) char g_wkh[8*32*TBB], g_wkl[8*32*TBB];
__device__ __align__(128) char g_wvh[8*32*TBB], g_wvl[8*32*TBB];
__device__ __align__(128) char g_woh[8*32*TBB], g_wol[8*32*TBB];
__device__ __align__(128) char g_pqh[128*32*TA], g_pql[128*32*TA];
__device__ __align__(128) char g_o1h[128*32*TA], g_o1l[128*32*TA];
__device__ __align__(128) char g_pkth[4*8*128*TA], g_pktl[4*8*128*TA];   // pk^T A-layout per batch
__device__ __align__(128) char g_pvh[4*8*128*TBB], g_pvl[4*8*128*TBB];   // pv B-layout per batch
__device__ __align__(128) char g_kvh[4*8*32*TBB], g_kvl[4*8*32*TBB];     // kv B-layout per batch

// ---------------- PTX helpers ----------------
__device__ __forceinline__ uint32_t s2u(const void* p) {
    uint32_t a;
    asm("{ .reg .u64 t; cvta.to.shared.u64 t, %1; cvt.u32.u64 %0, t; }" : "=r"(a) : "l"(p));
    return a;
}
#define MBARRIER_INIT(addr, cnt) \
    asm volatile("mbarrier.init.shared.b64 [%0], %1;" :: "r"((uint32_t)(addr)), "r"((uint32_t)(cnt)) : "memory")
#define MBARRIER_EXPECT_TX(addr, bytes) \
    asm volatile("mbarrier.arrive.expect_tx.shared.b64 _, [%0], %1;" :: "r"((uint32_t)(addr)), "r"((uint32_t)(bytes)) : "memory")
#define MBARRIER_WAIT_PARITY(mbar, par) do { \
    uint32_t _m = (uint32_t)(mbar); uint32_t _p = (uint32_t)(par); uint32_t _d; \
    asm volatile("{\n\t.reg .pred p;\n\tmbarrier.try_wait.parity.acquire.cta.shared::cta.b64 p, [%1], %2;\n\tselp.b32 %0, 1, 0, p;\n\t}" \
        : "=r"(_d) : "r"(_m), "r"(_p) : "memory"); \
    if (!_d) { \
        asm volatile("{\n\t.reg .pred P1;\n\tWL_%=:\n\tmbarrier.try_wait.parity.acquire.cta.shared::cta.b64 P1, [%0], %1, 0x989680;\n\t@P1 bra.uni WD_%=;\n\tbra.uni WL_%=;\n\tWD_%=:\n\t}" \
            :: "r"(_m), "r"(_p) : "memory"); \
    } \
} while(0)

__device__ __forceinline__ void bulk_g2s(uint32_t dst, const void* src, uint32_t bytes, uint32_t mbar) {
    asm volatile("cp.async.bulk.shared::cluster.global.mbarrier::complete_tx::bytes [%0], [%1], %2, [%3];"
        :: "r"(dst), "l"(src), "r"(bytes), "r"(mbar) : "memory");
}
__device__ __forceinline__ void ldsm4(uint32_t* r, uint32_t a) {
    asm volatile("ldmatrix.sync.aligned.m8n8.x4.shared.b16 {%0,%1,%2,%3}, [%4];"
        : "=r"(r[0]), "=r"(r[1]), "=r"(r[2]), "=r"(r[3]) : "r"(a));
}
__device__ __forceinline__ void ldsm4t(uint32_t* r, uint32_t a) {
    asm volatile("ldmatrix.sync.aligned.m8n8.x4.trans.shared.b16 {%0,%1,%2,%3}, [%4];"
        : "=r"(r[0]), "=r"(r[1]), "=r"(r[2]), "=r"(r[3]) : "r"(a));
}
__device__ __forceinline__ void mma16816(float* c, const uint32_t* a, const uint32_t* b) {
    asm volatile("mma.sync.aligned.m16n8k16.row.col.f32.bf16.bf16.f32 "
        "{%0,%1,%2,%3}, {%4,%5,%6,%7}, {%8,%9}, {%0,%1,%2,%3};"
        : "+f"(c[0]), "+f"(c[1]), "+f"(c[2]), "+f"(c[3])
        : "r"(a[0]), "r"(a[1]), "r"(a[2]), "r"(a[3]), "r"(b[0]), "r"(b[1]));
}

__device__ __forceinline__ unsigned short bfraw(bf16 h) { unsigned short u; memcpy(&u, &h, 2); return u; }
__device__ __forceinline__ void split2(float x, float y, uint32_t& H, uint32_t& L) {
    bf16 hx = __float2bfloat16(x), hy = __float2bfloat16(y);
    bf16 lx = __float2bfloat16(x - __bfloat162float(hx));
    bf16 ly = __float2bfloat16(y - __bfloat162float(hy));
    H = (uint32_t)bfraw(hx) | ((uint32_t)bfraw(hy) << 16);
    L = (uint32_t)bfraw(lx) | ((uint32_t)bfraw(ly) << 16);
}

// ---------------- conversions ----------------
__global__ void conv_acts(const float* __restrict__ q, const float* __restrict__ k,
                          const float* __restrict__ v) {
    int zz = blockIdx.y;
    const float* src = zz == 0 ? q : zz == 1 ? k : v;
    char* hi = zz == 0 ? g_qh : zz == 1 ? g_kh : g_vh;
    char* lo = zz == 0 ? g_ql : zz == 1 ? g_kl : g_vl;
    int idx = blockIdx.x * 256 + threadIdx.x;   // M*128
    int m = idx >> 7;
    int k0 = (idx & 127) << 3;
    const float4* s = reinterpret_cast<const float4*>(src + ((size_t)m << 10) + k0);
    float4 a = s[0], b = s[1];
    uint32_t h[4], l[4];
    split2(a.x, a.y, h[0], l[0]); split2(a.z, a.w, h[1], l[1]);
    split2(b.x, b.y, h[2], l[2]); split2(b.z, b.w, h[3], l[3]);
    size_t tile = ((size_t)(m >> 7) * 32 + (k0 >> 5)) * TA;
    uint32_t off = (uint32_t)(m & 127) * 80 + (k0 & 31) * 2;
    *reinterpret_cast<uint4*>(hi + tile + off) = make_uint4(h[0], h[1], h[2], h[3]);
    *reinterpret_cast<uint4*>(lo + tile + off) = make_uint4(l[0], l[1], l[2], l[3]);
}
__global__ void conv_ws(const float* __restrict__ Wq, const float* __restrict__ Wk,
                        const float* __restrict__ Wv, const float* __restrict__ Wo) {
    int zz = blockIdx.y;
    const float* W = zz == 0 ? Wq : zz == 1 ? Wk : zz == 2 ? Wv : Wo;
    char* hi = zz == 0 ? g_wqh : zz == 1 ? g_wkh : zz == 2 ? g_wvh : g_woh;
    char* lo = zz == 0 ? g_wql : zz == 1 ? g_wkl : zz == 2 ? g_wvl : g_wol;
    int idx = blockIdx.x * 256 + threadIdx.x;   // 1024*128
    int k = idx >> 7;
    int n0 = (idx & 127) << 3;
    const float4* s = reinterpret_cast<const float4*>(W + ((size_t)k << 10) + n0);
    float4 a = s[0], b = s[1];
    uint32_t h[4], l[4];
    split2(a.x, a.y, h[0], l[0]); split2(a.z, a.w, h[1], l[1]);
    split2(b.x, b.y, h[2], l[2]); split2(b.z, b.w, h[3], l[3]);
    size_t tile = ((size_t)(n0 >> 7) * 32 + (k >> 5)) * TBB;
    uint32_t off = (uint32_t)(k & 31) * 272 + (n0 & 127) * 2;
    *reinterpret_cast<uint4*>(hi + tile + off) = make_uint4(h[0], h[1], h[2], h[3]);
    *reinterpret_cast<uint4*>(lo + tile + off) = make_uint4(l[0], l[1], l[2], l[3]);
}

// ---------------- shared GEMM mainloop ----------------
__device__ __forceinline__ void refill(uint32_t st0, uint32_t sb, int s,
        const char* Abh, const char* Abl, const char* Bbh, const char* Bbl, int c) {
    MBARRIER_EXPECT_TX(sb + 8 * s, STG);
    uint32_t d = st0 + s * STG;
    bulk_g2s(d,            Abh + (size_t)c * TA,  TA,  sb + 8 * s);
    bulk_g2s(d + TA,       Abl + (size_t)c * TA,  TA,  sb + 8 * s);
    bulk_g2s(d + 2 * TA,   Bbh + (size_t)c * TBB, TBB, sb + 8 * s);
    bulk_g2s(d + 2*TA+TBB, Bbl + (size_t)c * TBB, TBB, sb + 8 * s);
}

__device__ __forceinline__ void gemm_core(
        const char* __restrict__ Abh, const char* __restrict__ Abl,
        const char* __restrict__ Bbh, const char* __restrict__ Bbl,
        int kch, uint32_t sb, uint32_t st0, float acc[4][4][4]) {
    const int tid = threadIdx.x, lane = tid & 31, wid = tid >> 5;
    const int wm = wid >> 2, wn = wid & 3;

    if (tid == 0)
        for (int s = 0; s < STAGES; ++s) MBARRIER_INIT(sb + 8 * s, 1);
    __syncthreads();

    if (tid == 0) {
        int np = STAGES < kch ? STAGES : kch;
        for (int s = 0; s < np; ++s) refill(st0, sb, s, Abh, Abl, Bbh, Bbl, s);
    }

#pragma unroll
    for (int i = 0; i < 4; i++)
#pragma unroll
        for (int j = 0; j < 4; j++)
#pragma unroll
            for (int r = 0; r < 4; r++) acc[i][j][r] = 0.0f;

    const uint32_t arow = (uint32_t)wm * 5120 + (uint32_t)(lane & 15) * 80 + (uint32_t)(lane >> 4) * 16;
    const uint32_t brow = (uint32_t)(lane & 15) * 272 + (uint32_t)wn * 64 + (uint32_t)(lane >> 4) * 16;

    for (int c = 0; c < kch; ++c) {
        int s = c % STAGES;
        int pf = (c / STAGES) & 1;
        MBARRIER_WAIT_PARITY(sb + 8 * s, pf);
        uint32_t sa = st0 + s * STG;
#pragma unroll
        for (int k16 = 0; k16 < 2; ++k16) {
            // B fragments first (16 regs live), then stream A per mf-group (8 regs live)
            uint32_t bb = sa + 2 * TA + brow + k16 * 4352;
            uint32_t bh[4][2], bl4[4][2], t[4];
            ldsm4t(t, bb);            bh[0][0]=t[0]; bh[0][1]=t[1]; bh[1][0]=t[2]; bh[1][1]=t[3];
            ldsm4t(t, bb + 32);       bh[2][0]=t[0]; bh[2][1]=t[1]; bh[3][0]=t[2]; bh[3][1]=t[3];
            ldsm4t(t, bb + TBB);      bl4[0][0]=t[0]; bl4[0][1]=t[1]; bl4[1][0]=t[2]; bl4[1][1]=t[3];
            ldsm4t(t, bb + TBB + 32); bl4[2][0]=t[0]; bl4[2][1]=t[1]; bl4[3][0]=t[2]; bl4[3][1]=t[3];
            uint32_t ab = sa + arow + k16 * 32;
#pragma unroll
            for (int mf = 0; mf < 4; ++mf) {
                uint32_t ah[4], al4[4];
                ldsm4(ah, ab + mf * 1280);
                ldsm4(al4, ab + TA + mf * 1280);
#pragma unroll
                for (int nf = 0; nf < 4; ++nf) {
                    mma16816(acc[mf][nf], ah, bh[nf]);
                    mma16816(acc[mf][nf], al4, bh[nf]);
                    mma16816(acc[mf][nf], ah, bl4[nf]);
                }
            }
        }
        __syncthreads();
        if (tid == 0 && c + STAGES < kch)
            refill(st0, sb, s, Abh, Abl, Bbh, Bbl, c + STAGES);
    }
}

// ---------------- GEMM kernels ----------------
// Projections: z=0 q->pq (A-layout), z=1 k->pkT (mask+swish, transposed), z=2 v->pv (mask, B-layout)
__global__ void __launch_bounds__(256, 2)
proj_gemm(const float* __restrict__ mask) {
    extern __shared__ __align__(1024) char smem[];
    uint32_t sb = s2u(smem), st0 = sb + 1024;
    const int tid = threadIdx.x, lane = tid & 31, wid = tid >> 5;
    const int wm = wid >> 2, wn = wid & 3;
    const int bx = blockIdx.x, by = blockIdx.y, z = blockIdx.z;
    const int m0 = by * 128;
    const int g = lane >> 2, tg = lane & 3;

    const char* Ah = z == 0 ? g_qh : z == 1 ? g_kh : g_vh;
    const char* Al = z == 0 ? g_ql : z == 1 ? g_kl : g_vl;
    const char* Bh = z == 0 ? g_wqh : z == 1 ? g_wkh : g_wvh;
    const char* Bl = z == 0 ? g_wql : z == 1 ? g_wkl : g_wvl;

    float acc[4][4][4];
    gemm_core(Ah + (size_t)by * 32 * TA, Al + (size_t)by * 32 * TA,
              Bh + (size_t)bx * 32 * TBB, Bl + (size_t)bx * 32 * TBB,
              32, sb, st0, acc);

    if (z == 0) {
        size_t mtile = ((size_t)by * 32 + bx * 4 + wn) * TA;
#pragma unroll
        for (int mf = 0; mf < 4; ++mf)
#pragma unroll
            for (int nf = 0; nf < 4; ++nf)
#pragma unroll
                for (int rh = 0; rh < 2; ++rh) {
                    int row = wm * 64 + mf * 16 + g + rh * 8;
                    uint32_t hw, lw;
                    split2(acc[mf][nf][rh * 2], acc[mf][nf][rh * 2 + 1], hw, lw);
                    uint32_t off = (uint32_t)row * 80 + (nf * 8 + tg * 2) * 2;
                    *reinterpret_cast<uint32_t*>(g_pqh + mtile + off) = hw;
                    *reinterpret_cast<uint32_t*>(g_pql + mtile + off) = lw;
                }
    } else if (z == 2) {
        int bt = by >> 5;
#pragma unroll
        for (int mf = 0; mf < 4; ++mf)
#pragma unroll
            for (int rh = 0; rh < 2; ++rh) {
                int row = wm * 64 + mf * 16 + g + rh * 8;
                float mv = mask[m0 + row];
                int kloc = (m0 & 4095) + row;
                size_t tile = ((size_t)(bt * 8 + bx) * 128 + (kloc >> 5)) * TBB;
                uint32_t rowoff = (uint32_t)(kloc & 31) * 272;
#pragma unroll
                for (int nf = 0; nf < 4; ++nf) {
                    uint32_t hw, lw;
                    split2(acc[mf][nf][rh * 2] * mv, acc[mf][nf][rh * 2 + 1] * mv, hw, lw);
                    uint32_t off = rowoff + (wn * 32 + nf * 8 + tg * 2) * 2;
                    *reinterpret_cast<uint32_t*>(g_pvh + tile + off) = hw;
                    *reinterpret_cast<uint32_t*>(g_pvl + tile + off) = lw;
                }
            }
    } else {
        // pk^T: mask + swish, transposed A-layout via smem staging
        uint32_t shh = st0, sll = st0 + 34816;
#pragma unroll
        for (int mf = 0; mf < 4; ++mf)
#pragma unroll
            for (int rh = 0; rh < 2; ++rh) {
                int row = wm * 64 + mf * 16 + g + rh * 8;
                float mv = mask[m0 + row];
#pragma unroll
                for (int nf = 0; nf < 4; ++nf) {
                    float v0 = acc[mf][nf][rh * 2] * mv;
                    float v1 = acc[mf][nf][rh * 2 + 1] * mv;
                    v0 = v0 / (1.0f + __expf(-v0));
                    v1 = v1 / (1.0f + __expf(-v1));
                    uint32_t hw, lw;
                    split2(v0, v1, hw, lw);
                    uint32_t a = (uint32_t)row * 272 + (wn * 32 + nf * 8 + tg * 2) * 2;
                    asm volatile("st.shared.b32 [%0], %1;" :: "r"(shh + a), "r"(hw) : "memory");
                    asm volatile("st.shared.b32 [%0], %1;" :: "r"(sll + a), "r"(lw) : "memory");
                }
            }
        __syncthreads();
        int u = tid & 127;
        int sh2 = (tid >> 7) * 64;
        int bt = by >> 5;
        int kc0 = (m0 & 4095) >> 5;
#pragma unroll
        for (int c8 = 0; c8 < 8; ++c8) {
            int s0 = sh2 + c8 * 8;
            uint32_t hw[4], lw[4];
#pragma unroll
            for (int p = 0; p < 4; ++p) {
                unsigned short h0, h1, l0, l1;
                uint32_t a0 = (uint32_t)(s0 + 2 * p) * 272 + (uint32_t)u * 2;
                uint32_t a1 = a0 + 272;
                asm volatile("ld.shared.b16 %0, [%1];" : "=h"(h0) : "r"(shh + a0));
                asm volatile("ld.shared.b16 %0, [%1];" : "=h"(h1) : "r"(shh + a1));
                asm volatile("ld.shared.b16 %0, [%1];" : "=h"(l0) : "r"(sll + a0));
                asm volatile("ld.shared.b16 %0, [%1];" : "=h"(l1) : "r"(sll + a1));
                hw[p] = (uint32_t)h0 | ((uint32_t)h1 << 16);
                lw[p] = (uint32_t)l0 | ((uint32_t)l1 << 16);
            }
            size_t tile = ((size_t)(bt * 8 + bx) * 128 + kc0 + (s0 >> 5)) * TA;
            uint32_t off = (uint32_t)u * 80 + (s0 & 31) * 2;
            *reinterpret_cast<uint4*>(g_pkth + tile + off) = make_uint4(hw[0], hw[1], hw[2], hw[3]);
            *reinterpret_cast<uint4*>(g_pktl + tile + off) = make_uint4(lw[0], lw[1], lw[2], lw[3]);
        }
    }
}

// kv[b] = pk^T @ pv  (M=1024, N=1024, K=4096) -> B-layout
__global__ void __launch_bounds__(256, 2)
kv_gemm() {
    extern __shared__ __align__(1024) char smem[];
    uint32_t sb = s2u(smem), st0 = sb + 1024;
    const int tid = threadIdx.x, lane = tid & 31, wid = tid >> 5;
    const int wm = wid >> 2, wn = wid & 3;
    const int bx = blockIdx.x, by = blockIdx.y, z = blockIdx.z;
    const int m0 = by * 128;
    const int g = lane >> 2, tg = lane & 3;

    float acc[4][4][4];
    gemm_core(g_pkth + (size_t)(z * 8 + by) * 128 * TA, g_pktl + (size_t)(z * 8 + by) * 128 * TA,
              g_pvh + (size_t)(z * 8 + bx) * 128 * TBB, g_pvl + (size_t)(z * 8 + bx) * 128 * TBB,
              128, sb, st0, acc);

#pragma unroll
    for (int mf = 0; mf < 4; ++mf)
#pragma unroll
        for (int rh = 0; rh < 2; ++rh) {
            int row = wm * 64 + mf * 16 + g + rh * 8;
            int kloc = m0 + row;
            size_t tile = ((size_t)(z * 8 + bx) * 32 + (kloc >> 5)) * TBB;
            uint32_t rowoff = (uint32_t)(kloc & 31) * 272;
#pragma unroll
            for (int nf = 0; nf < 4; ++nf) {
                uint32_t hw, lw;
                split2(acc[mf][nf][rh * 2], acc[mf][nf][rh * 2 + 1], hw, lw);
                uint32_t off = rowoff + (wn * 32 + nf * 8 + tg * 2) * 2;
                *reinterpret_cast<uint32_t*>(g_kvh + tile + off) = hw;
                *reinterpret_cast<uint32_t*>(g_kvl + tile + off) = lw;
            }
        }
}

// o1[b] = pq[b] @ kv[b] (M=4096, N=1024, K=1024) -> A-layout
__global__ void __launch_bounds__(256, 2)
o1_gemm() {
    extern __shared__ __align__(1024) char smem[];
    uint32_t sb = s2u(smem), st0 = sb + 1024;
    const int tid = threadIdx.x, lane = tid & 31, wid = tid >> 5;
    const int wm = wid >> 2, wn = wid & 3;
    const int bx = blockIdx.x, by = blockIdx.y, z = blockIdx.z;
    const int g = lane >> 2, tg = lane & 3;
    const int mb = z * 32 + by;

    float acc[4][4][4];
    gemm_core(g_pqh + (size_t)mb * 32 * TA, g_pql + (size_t)mb * 32 * TA,
              g_kvh + (size_t)(z * 8 + bx) * 32 * TBB, g_kvl + (size_t)(z * 8 + bx) * 32 * TBB,
              32, sb, st0, acc);

    size_t mtile = ((size_t)mb * 32 + bx * 4 + wn) * TA;
#pragma unroll
    for (int mf = 0; mf < 4; ++mf)
#pragma unroll
        for (int nf = 0; nf < 4; ++nf)
#pragma unroll
            for (int rh = 0; rh < 2; ++rh) {
                int row = wm * 64 + mf * 16 + g + rh * 8;
                uint32_t hw, lw;
                split2(acc[mf][nf][rh * 2], acc[mf][nf][rh * 2 + 1], hw, lw);
                uint32_t off = (uint32_t)row * 80 + (nf * 8 + tg * 2) * 2;
                *reinterpret_cast<uint32_t*>(g_o1h + mtile + off) = hw;
                *reinterpret_cast<uint32_t*>(g_o1l + mtile + off) = lw;
            }
}

// out = o1 @ Wo -> f32
__global__ void __launch_bounds__(256, 2)
wo_gemm(float* __restrict__ outF) {
    extern __shared__ __align__(1024) char smem[];
    uint32_t sb = s2u(smem), st0 = sb + 1024;
    const int tid = threadIdx.x, lane = tid & 31, wid = tid >> 5;
    const int wm = wid >> 2, wn = wid & 3;
    const int bx = blockIdx.x, by = blockIdx.y;
    const int m0 = by * 128, n0 = bx * 128;
    const int g = lane >> 2, tg = lane & 3;

    float acc[4][4][4];
    gemm_core(g_o1h + (size_t)by * 32 * TA, g_o1l + (size_t)by * 32 * TA,
              g_woh + (size_t)bx * 32 * TBB, g_wol + (size_t)bx * 32 * TBB,
              32, sb, st0, acc);

#pragma unroll
    for (int mf = 0; mf < 4; ++mf)
#pragma unroll
        for (int nf = 0; nf < 4; ++nf)
#pragma unroll
            for (int rh = 0; rh < 2; ++rh) {
                int row = wm * 64 + mf * 16 + g + rh * 8;
                int gcol = n0 + wn * 32 + nf * 8 + tg * 2;
                float2 v = make_float2(acc[mf][nf][rh * 2], acc[mf][nf][rh * 2 + 1]);
                *reinterpret_cast<float2*>(outF + (size_t)(m0 + row) * 1024 + gcol) = v;
            }
}

// ---------------- launch ----------------
extern "C" void kernel_launch(void* const* d_in, const int* in_sizes, int n_in,
                              void* d_out, int out_size) {
    const float* query = (const float*)d_in[0];
    const float* key   = (const float*)d_in[1];
    const float* value = (const float*)d_in[2];
    const float* mask  = (const float*)d_in[3];
    const float* Wk    = (const float*)d_in[4];
    const float* Wv    = (const float*)d_in[5];
    const float* Wq    = (const float*)d_in[6];
    const float* Wo    = (const float*)d_in[7];
    float* out = (float*)d_out;

    static bool attr_done = false;
    if (!attr_done) {
        cudaFuncSetAttribute(proj_gemm, cudaFuncAttributeMaxDynamicSharedMemorySize, SMEM_SZ);
        cudaFuncSetAttribute(kv_gemm,   cudaFuncAttributeMaxDynamicSharedMemorySize, SMEM_SZ);
        cudaFuncSetAttribute(o1_gemm,   cudaFuncAttributeMaxDynamicSharedMemorySize, SMEM_SZ);
        cudaFuncSetAttribute(wo_gemm,   cudaFuncAttributeMaxDynamicSharedMemorySize, SMEM_SZ);
        attr_done = true;
    }

    conv_acts<<<dim3(8192, 3), 256>>>(query, key, value);
    conv_ws<<<dim3(512, 4), 256>>>(Wq, Wk, Wv, Wo);

    proj_gemm<<<dim3(8, 128, 3), 256, SMEM_SZ>>>(mask);
    kv_gemm<<<dim3(8, 8, 4), 256, SMEM_SZ>>>();
    o1_gemm<<<dim3(8, 32, 4), 256, SMEM_SZ>>>();
    wo_gemm<<<dim3(8, 128, 1), 256, SMEM_SZ>>>(out);
}

// round 7
// speedup vs baseline: 4.8488x; 1.4902x over previous
#include <cuda_runtime.h>
#include <cuda_bf16.h>
#include <cstdint>
#include <string.h>
#include <math.h>

typedef __nv_bfloat16 bf16;

// Tile geometry: A tiles [128 rows][40 cols pad (32 real)] bf16 ; B tiles [32 rows][136 cols pad (128 real)]
#define TA 10240
#define TBB 8704
#define STG (2*TA + 2*TBB)     // 37888 per stage (Ah, Al, Bh, Bl)
#define STAGES 2
#define SMEM_SZ (1024 + STAGES*STG)   // 76800 -> 2 CTAs/SM

// ---------------- device-global scratch ----------------
__device__ __align__(128) char g_qh[128*32*TA], g_ql[128*32*TA];       // q  A-layout
__device__ __align__(128) char g_kh[128*32*TA], g_kl[128*32*TA];       // k  A-layout
__device__ __align__(128) char g_vbh[4*8*128*TBB], g_vbl[4*8*128*TBB]; // v  B-layout per batch
__device__ __align__(128) char g_wkh[8*32*TBB], g_wkl[8*32*TBB];       // Wk B-layout
__device__ __align__(128) char g_woh[8*32*TBB], g_wol[8*32*TBB];       // Wo B-layout
__device__ __align__(128) char g_wqh[8*32*TA],  g_wql[8*32*TA];        // Wq A-layout
__device__ __align__(128) char g_wvh[8*32*TA],  g_wvl[8*32*TA];        // Wv A-layout
__device__ __align__(128) char g_pkth[4*8*128*TA], g_pktl[4*8*128*TA]; // (swish(mask*kWk)*mask)^T A-layout
__device__ __align__(128) char g_wvwoh[8*32*TBB], g_wvwol[8*32*TBB];   // Wv@Wo B-layout
__device__ __align__(128) char g_kvrh[4*8*32*TA], g_kvrl[4*8*32*TA];   // pk3T@v A-layout per batch
__device__ __align__(128) char g_kvoh[4*8*32*TBB], g_kvol[4*8*32*TBB]; // kvr@WvWo B-layout per batch
__device__ __align__(128) char g_finh[4*8*32*TBB], g_finl[4*8*32*TBB]; // Wq@kvo B-layout per batch

// ---------------- PTX helpers ----------------
__device__ __forceinline__ uint32_t s2u(const void* p) {
    uint32_t a;
    asm("{ .reg .u64 t; cvta.to.shared.u64 t, %1; cvt.u32.u64 %0, t; }" : "=r"(a) : "l"(p));
    return a;
}
#define MBARRIER_INIT(addr, cnt) \
    asm volatile("mbarrier.init.shared.b64 [%0], %1;" :: "r"((uint32_t)(addr)), "r"((uint32_t)(cnt)) : "memory")
#define MBARRIER_EXPECT_TX(addr, bytes) \
    asm volatile("mbarrier.arrive.expect_tx.shared.b64 _, [%0], %1;" :: "r"((uint32_t)(addr)), "r"((uint32_t)(bytes)) : "memory")
#define MBARRIER_WAIT_PARITY(mbar, par) do { \
    uint32_t _m = (uint32_t)(mbar); uint32_t _p = (uint32_t)(par); uint32_t _d; \
    asm volatile("{\n\t.reg .pred p;\n\tmbarrier.try_wait.parity.acquire.cta.shared::cta.b64 p, [%1], %2;\n\tselp.b32 %0, 1, 0, p;\n\t}" \
        : "=r"(_d) : "r"(_m), "r"(_p) : "memory"); \
    if (!_d) { \
        asm volatile("{\n\t.reg .pred P1;\n\tWL_%=:\n\tmbarrier.try_wait.parity.acquire.cta.shared::cta.b64 P1, [%0], %1, 0x989680;\n\t@P1 bra.uni WD_%=;\n\tbra.uni WL_%=;\n\tWD_%=:\n\t}" \
            :: "r"(_m), "r"(_p) : "memory"); \
    } \
} while(0)

__device__ __forceinline__ void bulk_g2s(uint32_t dst, const void* src, uint32_t bytes, uint32_t mbar) {
    asm volatile("cp.async.bulk.shared::cluster.global.mbarrier::complete_tx::bytes [%0], [%1], %2, [%3];"
        :: "r"(dst), "l"(src), "r"(bytes), "r"(mbar) : "memory");
}
__device__ __forceinline__ void ldsm4(uint32_t* r, uint32_t a) {
    asm volatile("ldmatrix.sync.aligned.m8n8.x4.shared.b16 {%0,%1,%2,%3}, [%4];"
        : "=r"(r[0]), "=r"(r[1]), "=r"(r[2]), "=r"(r[3]) : "r"(a));
}
__device__ __forceinline__ void ldsm4t(uint32_t* r, uint32_t a) {
    asm volatile("ldmatrix.sync.aligned.m8n8.x4.trans.shared.b16 {%0,%1,%2,%3}, [%4];"
        : "=r"(r[0]), "=r"(r[1]), "=r"(r[2]), "=r"(r[3]) : "r"(a));
}
__device__ __forceinline__ void mma16816(float* c, const uint32_t* a, const uint32_t* b) {
    asm volatile("mma.sync.aligned.m16n8k16.row.col.f32.bf16.bf16.f32 "
        "{%0,%1,%2,%3}, {%4,%5,%6,%7}, {%8,%9}, {%0,%1,%2,%3};"
        : "+f"(c[0]), "+f"(c[1]), "+f"(c[2]), "+f"(c[3])
        : "r"(a[0]), "r"(a[1]), "r"(a[2]), "r"(a[3]), "r"(b[0]), "r"(b[1]));
}

__device__ __forceinline__ unsigned short bfraw(bf16 h) { unsigned short u; memcpy(&u, &h, 2); return u; }
__device__ __forceinline__ void split2(float x, float y, uint32_t& H, uint32_t& L) {
    bf16 hx = __float2bfloat16(x), hy = __float2bfloat16(y);
    bf16 lx = __float2bfloat16(x - __bfloat162float(hx));
    bf16 ly = __float2bfloat16(y - __bfloat162float(hy));
    H = (uint32_t)bfraw(hx) | ((uint32_t)bfraw(hy) << 16);
    L = (uint32_t)bfraw(lx) | ((uint32_t)bfraw(ly) << 16);
}

// ---------------- conversions ----------------
// z=0: q -> A-layout; z=1: k -> A-layout; z=2: v -> B-layout per batch
__global__ void conv_acts(const float* __restrict__ q, const float* __restrict__ k,
                          const float* __restrict__ v) {
    int zz = blockIdx.y;
    const float* src = zz == 0 ? q : zz == 1 ? k : v;
    int idx = blockIdx.x * 256 + threadIdx.x;   // 16384*128
    int m = idx >> 7;
    int u0 = (idx & 127) << 3;
    const float4* s = reinterpret_cast<const float4*>(src + ((size_t)m << 10) + u0);
    float4 a = s[0], b = s[1];
    uint32_t h[4], l[4];
    split2(a.x, a.y, h[0], l[0]); split2(a.z, a.w, h[1], l[1]);
    split2(b.x, b.y, h[2], l[2]); split2(b.z, b.w, h[3], l[3]);
    if (zz < 2) {
        char* hi = zz == 0 ? g_qh : g_kh;
        char* lo = zz == 0 ? g_ql : g_kl;
        size_t tile = ((size_t)(m >> 7) * 32 + (u0 >> 5)) * TA;
        uint32_t off = (uint32_t)(m & 127) * 80 + (u0 & 31) * 2;
        *reinterpret_cast<uint4*>(hi + tile + off) = make_uint4(h[0], h[1], h[2], h[3]);
        *reinterpret_cast<uint4*>(lo + tile + off) = make_uint4(l[0], l[1], l[2], l[3]);
    } else {
        int batch = m >> 12, sloc = m & 4095;
        size_t tile = ((size_t)(batch * 8 + (u0 >> 7)) * 128 + (sloc >> 5)) * TBB;
        uint32_t off = (uint32_t)(sloc & 31) * 272 + (u0 & 127) * 2;
        *reinterpret_cast<uint4*>(g_vbh + tile + off) = make_uint4(h[0], h[1], h[2], h[3]);
        *reinterpret_cast<uint4*>(g_vbl + tile + off) = make_uint4(l[0], l[1], l[2], l[3]);
    }
}
// z=0: Wk B-layout; z=1: Wo B-layout; z=2: Wq A-layout; z=3: Wv A-layout
__global__ void conv_ws(const float* __restrict__ Wk, const float* __restrict__ Wo,
                        const float* __restrict__ Wq, const float* __restrict__ Wv) {
    int zz = blockIdx.y;
    const float* W = zz == 0 ? Wk : zz == 1 ? Wo : zz == 2 ? Wq : Wv;
    int idx = blockIdx.x * 256 + threadIdx.x;   // 1024*128
    int r = idx >> 7;
    int c0 = (idx & 127) << 3;
    const float4* s = reinterpret_cast<const float4*>(W + ((size_t)r << 10) + c0);
    float4 a = s[0], b = s[1];
    uint32_t h[4], l[4];
    split2(a.x, a.y, h[0], l[0]); split2(a.z, a.w, h[1], l[1]);
    split2(b.x, b.y, h[2], l[2]); split2(b.z, b.w, h[3], l[3]);
    if (zz < 2) {
        // B-layout: r = k row, c = n col
        char* hi = zz == 0 ? g_wkh : g_woh;
        char* lo = zz == 0 ? g_wkl : g_wol;
        size_t tile = ((size_t)(c0 >> 7) * 32 + (r >> 5)) * TBB;
        uint32_t off = (uint32_t)(r & 31) * 272 + (c0 & 127) * 2;
        *reinterpret_cast<uint4*>(hi + tile + off) = make_uint4(h[0], h[1], h[2], h[3]);
        *reinterpret_cast<uint4*>(lo + tile + off) = make_uint4(l[0], l[1], l[2], l[3]);
    } else {
        // A-layout: r = m row, c = k col
        char* hi = zz == 2 ? g_wqh : g_wvh;
        char* lo = zz == 2 ? g_wql : g_wvl;
        size_t tile = ((size_t)(r >> 7) * 32 + (c0 >> 5)) * TA;
        uint32_t off = (uint32_t)(r & 127) * 80 + (c0 & 31) * 2;
        *reinterpret_cast<uint4*>(hi + tile + off) = make_uint4(h[0], h[1], h[2], h[3]);
        *reinterpret_cast<uint4*>(lo + tile + off) = make_uint4(l[0], l[1], l[2], l[3]);
    }
}

// ---------------- shared GEMM mainloop ----------------
__device__ __forceinline__ void refill(uint32_t st0, uint32_t sb, int s,
        const char* Abh, const char* Abl, const char* Bbh, const char* Bbl, int c) {
    MBARRIER_EXPECT_TX(sb + 8 * s, STG);
    uint32_t d = st0 + s * STG;
    bulk_g2s(d,            Abh + (size_t)c * TA,  TA,  sb + 8 * s);
    bulk_g2s(d + TA,       Abl + (size_t)c * TA,  TA,  sb + 8 * s);
    bulk_g2s(d + 2 * TA,   Bbh + (size_t)c * TBB, TBB, sb + 8 * s);
    bulk_g2s(d + 2*TA+TBB, Bbl + (size_t)c * TBB, TBB, sb + 8 * s);
}

__device__ __forceinline__ void gemm_core(
        const char* __restrict__ Abh, const char* __restrict__ Abl,
        const char* __restrict__ Bbh, const char* __restrict__ Bbl,
        int kch, uint32_t sb, uint32_t st0, float acc[4][4][4]) {
    const int tid = threadIdx.x, lane = tid & 31, wid = tid >> 5;
    const int wm = wid >> 2, wn = wid & 3;

    if (tid == 0)
        for (int s = 0; s < STAGES; ++s) MBARRIER_INIT(sb + 8 * s, 1);
    __syncthreads();

    if (tid == 0) {
        int np = STAGES < kch ? STAGES : kch;
        for (int s = 0; s < np; ++s) refill(st0, sb, s, Abh, Abl, Bbh, Bbl, s);
    }

#pragma unroll
    for (int i = 0; i < 4; i++)
#pragma unroll
        for (int j = 0; j < 4; j++)
#pragma unroll
            for (int r = 0; r < 4; r++) acc[i][j][r] = 0.0f;

    const uint32_t arow = (uint32_t)wm * 5120 + (uint32_t)(lane & 15) * 80 + (uint32_t)(lane >> 4) * 16;
    const uint32_t brow = (uint32_t)(lane & 15) * 272 + (uint32_t)wn * 64 + (uint32_t)(lane >> 4) * 16;

    for (int c = 0; c < kch; ++c) {
        int s = c % STAGES;
        int pf = (c / STAGES) & 1;
        MBARRIER_WAIT_PARITY(sb + 8 * s, pf);
        uint32_t sa = st0 + s * STG;
#pragma unroll
        for (int k16 = 0; k16 < 2; ++k16) {
            uint32_t bb = sa + 2 * TA + brow + k16 * 4352;
            uint32_t bh[4][2], bl4[4][2], t[4];
            ldsm4t(t, bb);            bh[0][0]=t[0]; bh[0][1]=t[1]; bh[1][0]=t[2]; bh[1][1]=t[3];
            ldsm4t(t, bb + 32);       bh[2][0]=t[0]; bh[2][1]=t[1]; bh[3][0]=t[2]; bh[3][1]=t[3];
            ldsm4t(t, bb + TBB);      bl4[0][0]=t[0]; bl4[0][1]=t[1]; bl4[1][0]=t[2]; bl4[1][1]=t[3];
            ldsm4t(t, bb + TBB + 32); bl4[2][0]=t[0]; bl4[2][1]=t[1]; bl4[3][0]=t[2]; bl4[3][1]=t[3];
            uint32_t ab = sa + arow + k16 * 32;
#pragma unroll
            for (int mf = 0; mf < 4; ++mf) {
                uint32_t ah[4], al4[4];
                ldsm4(ah, ab + mf * 1280);
                ldsm4(al4, ab + TA + mf * 1280);
#pragma unroll
                for (int nf = 0; nf < 4; ++nf) {
                    mma16816(acc[mf][nf], ah, bh[nf]);
                    mma16816(acc[mf][nf], al4, bh[nf]);
                    mma16816(acc[mf][nf], ah, bl4[nf]);
                }
            }
        }
        __syncthreads();
        if (tid == 0 && c + STAGES < kch)
            refill(st0, sb, s, Abh, Abl, Bbh, Bbl, c + STAGES);
    }
}

// ---------------- epilogue helpers ----------------
// A-layout split store: block result rows -> A rows, cols -> k
__device__ __forceinline__ void epi_alayout(float acc[4][4][4], char* outH, char* outL,
                                            size_t mtile_base) {
    const int lane = threadIdx.x & 31, wid = threadIdx.x >> 5;
    const int wm = wid >> 2, wn = wid & 3;
    const int g = lane >> 2, tg = lane & 3;
    size_t mtile = (mtile_base + wn) * TA;
#pragma unroll
    for (int mf = 0; mf < 4; ++mf)
#pragma unroll
        for (int nf = 0; nf < 4; ++nf)
#pragma unroll
            for (int rh = 0; rh < 2; ++rh) {
                int row = wm * 64 + mf * 16 + g + rh * 8;
                uint32_t hw, lw;
                split2(acc[mf][nf][rh * 2], acc[mf][nf][rh * 2 + 1], hw, lw);
                uint32_t off = (uint32_t)row * 80 + (nf * 8 + tg * 2) * 2;
                *reinterpret_cast<uint32_t*>(outH + mtile + off) = hw;
                *reinterpret_cast<uint32_t*>(outL + mtile + off) = lw;
            }
}
// B-layout split store: block rows -> k of B, cols -> n. nkbase = (nblk_global)*32 tiles
__device__ __forceinline__ void epi_blayout(float acc[4][4][4], char* outH, char* outL,
                                            size_t nkbase, int m0) {
    const int lane = threadIdx.x & 31, wid = threadIdx.x >> 5;
    const int wm = wid >> 2, wn = wid & 3;
    const int g = lane >> 2, tg = lane & 3;
#pragma unroll
    for (int mf = 0; mf < 4; ++mf)
#pragma unroll
        for (int rh = 0; rh < 2; ++rh) {
            int row = wm * 64 + mf * 16 + g + rh * 8;
            int kloc = m0 + row;
            size_t tile = (nkbase + (kloc >> 5)) * TBB;
            uint32_t rowoff = (uint32_t)(kloc & 31) * 272;
#pragma unroll
            for (int nf = 0; nf < 4; ++nf) {
                uint32_t hw, lw;
                split2(acc[mf][nf][rh * 2], acc[mf][nf][rh * 2 + 1], hw, lw);
                uint32_t off = rowoff + (wn * 32 + nf * 8 + tg * 2) * 2;
                *reinterpret_cast<uint32_t*>(outH + tile + off) = hw;
                *reinterpret_cast<uint32_t*>(outL + tile + off) = lw;
            }
        }
}

// ---------------- GEMM kernels ----------------
// pk3T = (swish(mask*(k@Wk)) * mask)^T  -> transposed A-layout per batch
__global__ void __launch_bounds__(256, 2)
projk_gemm(const float* __restrict__ mask) {
    extern __shared__ __align__(1024) char smem[];
    uint32_t sb = s2u(smem), st0 = sb + 1024;
    const int tid = threadIdx.x, lane = tid & 31, wid = tid >> 5;
    const int wm = wid >> 2, wn = wid & 3;
    const int bx = blockIdx.x, by = blockIdx.y;
    const int m0 = by * 128;
    const int g = lane >> 2, tg = lane & 3;

    float acc[4][4][4];
    gemm_core(g_kh + (size_t)by * 32 * TA, g_kl + (size_t)by * 32 * TA,
              g_wkh + (size_t)bx * 32 * TBB, g_wkl + (size_t)bx * 32 * TBB,
              32, sb, st0, acc);

    uint32_t shh = st0, sll = st0 + 34816;
#pragma unroll
    for (int mf = 0; mf < 4; ++mf)
#pragma unroll
        for (int rh = 0; rh < 2; ++rh) {
            int row = wm * 64 + mf * 16 + g + rh * 8;
            float mv = mask[m0 + row];
#pragma unroll
            for (int nf = 0; nf < 4; ++nf) {
                float v0 = acc[mf][nf][rh * 2] * mv;
                float v1 = acc[mf][nf][rh * 2 + 1] * mv;
                v0 = v0 / (1.0f + __expf(-v0)) * mv;   // swish, then fold pv's mask
                v1 = v1 / (1.0f + __expf(-v1)) * mv;
                uint32_t hw, lw;
                split2(v0, v1, hw, lw);
                uint32_t a = (uint32_t)row * 272 + (wn * 32 + nf * 8 + tg * 2) * 2;
                asm volatile("st.shared.b32 [%0], %1;" :: "r"(shh + a), "r"(hw) : "memory");
                asm volatile("st.shared.b32 [%0], %1;" :: "r"(sll + a), "r"(lw) : "memory");
            }
        }
    __syncthreads();
    int u = tid & 127;
    int sh2 = (tid >> 7) * 64;
    int bt = by >> 5;
    int kc0 = (m0 & 4095) >> 5;
#pragma unroll
    for (int c8 = 0; c8 < 8; ++c8) {
        int s0 = sh2 + c8 * 8;
        uint32_t hw[4], lw[4];
#pragma unroll
        for (int p = 0; p < 4; ++p) {
            unsigned short h0, h1, l0, l1;
            uint32_t a0 = (uint32_t)(s0 + 2 * p) * 272 + (uint32_t)u * 2;
            uint32_t a1 = a0 + 272;
            asm volatile("ld.shared.b16 %0, [%1];" : "=h"(h0) : "r"(shh + a0));
            asm volatile("ld.shared.b16 %0, [%1];" : "=h"(h1) : "r"(shh + a1));
            asm volatile("ld.shared.b16 %0, [%1];" : "=h"(l0) : "r"(sll + a0));
            asm volatile("ld.shared.b16 %0, [%1];" : "=h"(l1) : "r"(sll + a1));
            hw[p] = (uint32_t)h0 | ((uint32_t)h1 << 16);
            lw[p] = (uint32_t)l0 | ((uint32_t)l1 << 16);
        }
        size_t tile = ((size_t)(bt * 8 + bx) * 128 + kc0 + (s0 >> 5)) * TA;
        uint32_t off = (uint32_t)u * 80 + (s0 & 31) * 2;
        *reinterpret_cast<uint4*>(g_pkth + tile + off) = make_uint4(hw[0], hw[1], hw[2], hw[3]);
        *reinterpret_cast<uint4*>(g_pktl + tile + off) = make_uint4(lw[0], lw[1], lw[2], lw[3]);
    }
}

// WvWo = Wv @ Wo  -> B-layout (single)
__global__ void __launch_bounds__(256, 2)
wvwo_gemm() {
    extern __shared__ __align__(1024) char smem[];
    uint32_t sb = s2u(smem), st0 = sb + 1024;
    const int bx = blockIdx.x, by = blockIdx.y;
    float acc[4][4][4];
    gemm_core(g_wvh + (size_t)by * 32 * TA, g_wvl + (size_t)by * 32 * TA,
              g_woh + (size_t)bx * 32 * TBB, g_wol + (size_t)bx * 32 * TBB,
              32, sb, st0, acc);
    epi_blayout(acc, g_wvwoh, g_wvwol, (size_t)bx * 32, by * 128);
}

// kvr[b] = pk3T[b] @ v[b]  (M=1024,N=1024,K=4096) -> A-layout per batch
__global__ void __launch_bounds__(256, 2)
kvr_gemm() {
    extern __shared__ __align__(1024) char smem[];
    uint32_t sb = s2u(smem), st0 = sb + 1024;
    const int bx = blockIdx.x, by = blockIdx.y, z = blockIdx.z;
    float acc[4][4][4];
    gemm_core(g_pkth + (size_t)(z * 8 + by) * 128 * TA, g_pktl + (size_t)(z * 8 + by) * 128 * TA,
              g_vbh + (size_t)(z * 8 + bx) * 128 * TBB, g_vbl + (size_t)(z * 8 + bx) * 128 * TBB,
              128, sb, st0, acc);
    epi_alayout(acc, g_kvrh, g_kvrl, (size_t)(z * 8 + by) * 32 + bx * 4);
}

// kvo[b] = kvr[b] @ WvWo  (1024^3) -> B-layout per batch
__global__ void __launch_bounds__(256, 2)
kvo_gemm() {
    extern __shared__ __align__(1024) char smem[];
    uint32_t sb = s2u(smem), st0 = sb + 1024;
    const int bx = blockIdx.x, by = blockIdx.y, z = blockIdx.z;
    float acc[4][4][4];
    gemm_core(g_kvrh + (size_t)(z * 8 + by) * 32 * TA, g_kvrl + (size_t)(z * 8 + by) * 32 * TA,
              g_wvwoh + (size_t)bx * 32 * TBB, g_wvwol + (size_t)bx * 32 * TBB,
              32, sb, st0, acc);
    epi_blayout(acc, g_kvoh, g_kvol, (size_t)(z * 8 + bx) * 32, by * 128);
}

// fin[b] = Wq @ kvo[b]  (1024^3) -> B-layout per batch
__global__ void __launch_bounds__(256, 2)
wqkvo_gemm() {
    extern __shared__ __align__(1024) char smem[];
    uint32_t sb = s2u(smem), st0 = sb + 1024;
    const int bx = blockIdx.x, by = blockIdx.y, z = blockIdx.z;
    float acc[4][4][4];
    gemm_core(g_wqh + (size_t)by * 32 * TA, g_wql + (size_t)by * 32 * TA,
              g_kvoh + (size_t)(z * 8 + bx) * 32 * TBB, g_kvol + (size_t)(z * 8 + bx) * 32 * TBB,
              32, sb, st0, acc);
    epi_blayout(acc, g_finh, g_finl, (size_t)(z * 8 + bx) * 32, by * 128);
}

// out = q @ fin  (per batch, M=4096,N=1024,K=1024) -> f32
__global__ void __launch_bounds__(256, 2)
final_gemm(float* __restrict__ outF) {
    extern __shared__ __align__(1024) char smem[];
    uint32_t sb = s2u(smem), st0 = sb + 1024;
    const int tid = threadIdx.x, lane = tid & 31, wid = tid >> 5;
    const int wm = wid >> 2, wn = wid & 3;
    const int bx = blockIdx.x, by = blockIdx.y, z = blockIdx.z;
    const int g = lane >> 2, tg = lane & 3;
    const int mb = z * 32 + by;
    const int n0 = bx * 128;

    float acc[4][4][4];
    gemm_core(g_qh + (size_t)mb * 32 * TA, g_ql + (size_t)mb * 32 * TA,
              g_finh + (size_t)(z * 8 + bx) * 32 * TBB, g_finl + (size_t)(z * 8 + bx) * 32 * TBB,
              32, sb, st0, acc);

#pragma unroll
    for (int mf = 0; mf < 4; ++mf)
#pragma unroll
        for (int nf = 0; nf < 4; ++nf)
#pragma unroll
            for (int rh = 0; rh < 2; ++rh) {
                int row = wm * 64 + mf * 16 + g + rh * 8;
                int gcol = n0 + wn * 32 + nf * 8 + tg * 2;
                float2 v = make_float2(acc[mf][nf][rh * 2], acc[mf][nf][rh * 2 + 1]);
                *reinterpret_cast<float2*>(outF + ((size_t)mb * 128 + row) * 1024 + gcol) = v;
            }
}

// ---------------- launch ----------------
extern "C" void kernel_launch(void* const* d_in, const int* in_sizes, int n_in,
                              void* d_out, int out_size) {
    const float* query = (const float*)d_in[0];
    const float* key   = (const float*)d_in[1];
    const float* value = (const float*)d_in[2];
    const float* mask  = (const float*)d_in[3];
    const float* Wk    = (const float*)d_in[4];
    const float* Wv    = (const float*)d_in[5];
    const float* Wq    = (const float*)d_in[6];
    const float* Wo    = (const float*)d_in[7];
    float* out = (float*)d_out;

    static bool attr_done = false;
    if (!attr_done) {
        cudaFuncSetAttribute(projk_gemm, cudaFuncAttributeMaxDynamicSharedMemorySize, SMEM_SZ);
        cudaFuncSetAttribute(wvwo_gemm,  cudaFuncAttributeMaxDynamicSharedMemorySize, SMEM_SZ);
        cudaFuncSetAttribute(kvr_gemm,   cudaFuncAttributeMaxDynamicSharedMemorySize, SMEM_SZ);
        cudaFuncSetAttribute(kvo_gemm,   cudaFuncAttributeMaxDynamicSharedMemorySize, SMEM_SZ);
        cudaFuncSetAttribute(wqkvo_gemm, cudaFuncAttributeMaxDynamicSharedMemorySize, SMEM_SZ);
        cudaFuncSetAttribute(final_gemm, cudaFuncAttributeMaxDynamicSharedMemorySize, SMEM_SZ);
        attr_done = true;
    }

    conv_acts<<<dim3(8192, 3), 256>>>(query, key, value);
    conv_ws<<<dim3(512, 4), 256>>>(Wk, Wo, Wq, Wv);

    wvwo_gemm<<<dim3(8, 8, 1), 256, SMEM_SZ>>>();
    projk_gemm<<<dim3(8, 128, 1), 256, SMEM_SZ>>>(mask);
    kvr_gemm<<<dim3(8, 8, 4), 256, SMEM_SZ>>>();
    kvo_gemm<<<dim3(8, 8, 4), 256, SMEM_SZ>>>();
    wqkvo_gemm<<<dim3(8, 8, 4), 256, SMEM_SZ>>>();
    final_gemm<<<dim3(8, 32, 4), 256, SMEM_SZ>>>(out);
}

// round 8
// speedup vs baseline: 4.8918x; 1.0089x over previous
#include <cuda_runtime.h>
#include <cuda_bf16.h>
#include <cstdint>
#include <string.h>
#include <math.h>

typedef __nv_bfloat16 bf16;

// Tile geometry: A tiles [128 rows][40 cols pad (32 real)] bf16 ; B tiles [32 rows][136 cols pad (128 real)]
#define TA 10240
#define TBB 8704
#define STG (2*TA + 2*TBB)     // 37888 per stage (Ah, Al, Bh, Bl)
#define STAGES 3
#define SMEM_SZ (1024 + STAGES*STG)   // 114688 -> still 2 CTAs/SM (229376 <= 228KB)

// ---------------- device-global scratch ----------------
__device__ __align__(128) char g_qh[128*32*TA], g_ql[128*32*TA];       // q  A-layout
__device__ __align__(128) char g_kh[128*32*TA], g_kl[128*32*TA];       // k  A-layout
__device__ __align__(128) char g_vbh[4*8*128*TBB], g_vbl[4*8*128*TBB]; // v  B-layout per batch
__device__ __align__(128) char g_wkh[8*32*TBB], g_wkl[8*32*TBB];       // Wk B-layout
__device__ __align__(128) char g_woh[8*32*TBB], g_wol[8*32*TBB];       // Wo B-layout
__device__ __align__(128) char g_wqh[8*32*TA],  g_wql[8*32*TA];        // Wq A-layout
__device__ __align__(128) char g_wvh[8*32*TA],  g_wvl[8*32*TA];        // Wv A-layout
__device__ __align__(128) char g_pkth[4*8*128*TA], g_pktl[4*8*128*TA]; // (swish(mask*kWk)*mask)^T A-layout
__device__ __align__(128) char g_wvwoh[8*32*TBB], g_wvwol[8*32*TBB];   // Wv@Wo B-layout
__device__ __align__(128) char g_kvrh[4*8*32*TA], g_kvrl[4*8*32*TA];   // pk3T@v A-layout per batch
__device__ __align__(128) char g_kvoh[4*8*32*TBB], g_kvol[4*8*32*TBB]; // kvr@WvWo B-layout per batch
__device__ __align__(128) char g_finh[4*8*32*TBB], g_finl[4*8*32*TBB]; // Wq@kvo B-layout per batch

// ---------------- PTX helpers ----------------
__device__ __forceinline__ uint32_t s2u(const void* p) {
    uint32_t a;
    asm("{ .reg .u64 t; cvta.to.shared.u64 t, %1; cvt.u32.u64 %0, t; }" : "=r"(a) : "l"(p));
    return a;
}
#define MBARRIER_INIT(addr, cnt) \
    asm volatile("mbarrier.init.shared.b64 [%0], %1;" :: "r"((uint32_t)(addr)), "r"((uint32_t)(cnt)) : "memory")
#define MBARRIER_EXPECT_TX(addr, bytes) \
    asm volatile("mbarrier.arrive.expect_tx.shared.b64 _, [%0], %1;" :: "r"((uint32_t)(addr)), "r"((uint32_t)(bytes)) : "memory")
#define MBARRIER_ARRIVE(addr) \
    asm volatile("mbarrier.arrive.release.cta.shared::cta.b64 _, [%0];" :: "r"((uint32_t)(addr)) : "memory")
#define MBARRIER_WAIT_PARITY(mbar, par) do { \
    uint32_t _m = (uint32_t)(mbar); uint32_t _p = (uint32_t)(par); uint32_t _d; \
    asm volatile("{\n\t.reg .pred p;\n\tmbarrier.try_wait.parity.acquire.cta.shared::cta.b64 p, [%1], %2;\n\tselp.b32 %0, 1, 0, p;\n\t}" \
        : "=r"(_d) : "r"(_m), "r"(_p) : "memory"); \
    if (!_d) { \
        asm volatile("{\n\t.reg .pred P1;\n\tWL_%=:\n\tmbarrier.try_wait.parity.acquire.cta.shared::cta.b64 P1, [%0], %1, 0x989680;\n\t@P1 bra.uni WD_%=;\n\tbra.uni WL_%=;\n\tWD_%=:\n\t}" \
            :: "r"(_m), "r"(_p) : "memory"); \
    } \
} while(0)

__device__ __forceinline__ void bulk_g2s(uint32_t dst, const void* src, uint32_t bytes, uint32_t mbar) {
    asm volatile("cp.async.bulk.shared::cluster.global.mbarrier::complete_tx::bytes [%0], [%1], %2, [%3];"
        :: "r"(dst), "l"(src), "r"(bytes), "r"(mbar) : "memory");
}
__device__ __forceinline__ void ldsm4(uint32_t* r, uint32_t a) {
    asm volatile("ldmatrix.sync.aligned.m8n8.x4.shared.b16 {%0,%1,%2,%3}, [%4];"
        : "=r"(r[0]), "=r"(r[1]), "=r"(r[2]), "=r"(r[3]) : "r"(a));
}
__device__ __forceinline__ void ldsm4t(uint32_t* r, uint32_t a) {
    asm volatile("ldmatrix.sync.aligned.m8n8.x4.trans.shared.b16 {%0,%1,%2,%3}, [%4];"
        : "=r"(r[0]), "=r"(r[1]), "=r"(r[2]), "=r"(r[3]) : "r"(a));
}
__device__ __forceinline__ void mma16816(float* c, const uint32_t* a, const uint32_t* b) {
    asm volatile("mma.sync.aligned.m16n8k16.row.col.f32.bf16.bf16.f32 "
        "{%0,%1,%2,%3}, {%4,%5,%6,%7}, {%8,%9}, {%0,%1,%2,%3};"
        : "+f"(c[0]), "+f"(c[1]), "+f"(c[2]), "+f"(c[3])
        : "r"(a[0]), "r"(a[1]), "r"(a[2]), "r"(a[3]), "r"(b[0]), "r"(b[1]));
}

__device__ __forceinline__ unsigned short bfraw(bf16 h) { unsigned short u; memcpy(&u, &h, 2); return u; }
__device__ __forceinline__ void split2(float x, float y, uint32_t& H, uint32_t& L) {
    bf16 hx = __float2bfloat16(x), hy = __float2bfloat16(y);
    bf16 lx = __float2bfloat16(x - __bfloat162float(hx));
    bf16 ly = __float2bfloat16(y - __bfloat162float(hy));
    H = (uint32_t)bfraw(hx) | ((uint32_t)bfraw(hy) << 16);
    L = (uint32_t)bfraw(lx) | ((uint32_t)bfraw(ly) << 16);
}

// ---------------- conversions ----------------
// z=0: q -> A-layout; z=1: k -> A-layout; z=2: v -> B-layout per batch
__global__ void conv_acts(const float* __restrict__ q, const float* __restrict__ k,
                          const float* __restrict__ v) {
    int zz = blockIdx.y;
    const float* src = zz == 0 ? q : zz == 1 ? k : v;
    int idx = blockIdx.x * 256 + threadIdx.x;   // 16384*128
    int m = idx >> 7;
    int u0 = (idx & 127) << 3;
    const float4* s = reinterpret_cast<const float4*>(src + ((size_t)m << 10) + u0);
    float4 a = s[0], b = s[1];
    uint32_t h[4], l[4];
    split2(a.x, a.y, h[0], l[0]); split2(a.z, a.w, h[1], l[1]);
    split2(b.x, b.y, h[2], l[2]); split2(b.z, b.w, h[3], l[3]);
    if (zz < 2) {
        char* hi = zz == 0 ? g_qh : g_kh;
        char* lo = zz == 0 ? g_ql : g_kl;
        size_t tile = ((size_t)(m >> 7) * 32 + (u0 >> 5)) * TA;
        uint32_t off = (uint32_t)(m & 127) * 80 + (u0 & 31) * 2;
        *reinterpret_cast<uint4*>(hi + tile + off) = make_uint4(h[0], h[1], h[2], h[3]);
        *reinterpret_cast<uint4*>(lo + tile + off) = make_uint4(l[0], l[1], l[2], l[3]);
    } else {
        int batch = m >> 12, sloc = m & 4095;
        size_t tile = ((size_t)(batch * 8 + (u0 >> 7)) * 128 + (sloc >> 5)) * TBB;
        uint32_t off = (uint32_t)(sloc & 31) * 272 + (u0 & 127) * 2;
        *reinterpret_cast<uint4*>(g_vbh + tile + off) = make_uint4(h[0], h[1], h[2], h[3]);
        *reinterpret_cast<uint4*>(g_vbl + tile + off) = make_uint4(l[0], l[1], l[2], l[3]);
    }
}
// z=0: Wk B-layout; z=1: Wo B-layout; z=2: Wq A-layout; z=3: Wv A-layout
__global__ void conv_ws(const float* __restrict__ Wk, const float* __restrict__ Wo,
                        const float* __restrict__ Wq, const float* __restrict__ Wv) {
    int zz = blockIdx.y;
    const float* W = zz == 0 ? Wk : zz == 1 ? Wo : zz == 2 ? Wq : Wv;
    int idx = blockIdx.x * 256 + threadIdx.x;   // 1024*128
    int r = idx >> 7;
    int c0 = (idx & 127) << 3;
    const float4* s = reinterpret_cast<const float4*>(W + ((size_t)r << 10) + c0);
    float4 a = s[0], b = s[1];
    uint32_t h[4], l[4];
    split2(a.x, a.y, h[0], l[0]); split2(a.z, a.w, h[1], l[1]);
    split2(b.x, b.y, h[2], l[2]); split2(b.z, b.w, h[3], l[3]);
    if (zz < 2) {
        char* hi = zz == 0 ? g_wkh : g_woh;
        char* lo = zz == 0 ? g_wkl : g_wol;
        size_t tile = ((size_t)(c0 >> 7) * 32 + (r >> 5)) * TBB;
        uint32_t off = (uint32_t)(r & 31) * 272 + (c0 & 127) * 2;
        *reinterpret_cast<uint4*>(hi + tile + off) = make_uint4(h[0], h[1], h[2], h[3]);
        *reinterpret_cast<uint4*>(lo + tile + off) = make_uint4(l[0], l[1], l[2], l[3]);
    } else {
        char* hi = zz == 2 ? g_wqh : g_wvh;
        char* lo = zz == 2 ? g_wql : g_wvl;
        size_t tile = ((size_t)(r >> 7) * 32 + (c0 >> 5)) * TA;
        uint32_t off = (uint32_t)(r & 127) * 80 + (c0 & 31) * 2;
        *reinterpret_cast<uint4*>(hi + tile + off) = make_uint4(h[0], h[1], h[2], h[3]);
        *reinterpret_cast<uint4*>(lo + tile + off) = make_uint4(l[0], l[1], l[2], l[3]);
    }
}

// ---------------- shared GEMM mainloop ----------------
// Barrier layout: full[s] at sb+16*s, empty[s] at sb+16*s+8.
__device__ __forceinline__ void refill(uint32_t st0, uint32_t sb, int s,
        const char* Abh, const char* Abl, const char* Bbh, const char* Bbl, int c) {
    MBARRIER_EXPECT_TX(sb + 16 * s, STG);
    uint32_t d = st0 + s * STG;
    bulk_g2s(d,            Abh + (size_t)c * TA,  TA,  sb + 16 * s);
    bulk_g2s(d + TA,       Abl + (size_t)c * TA,  TA,  sb + 16 * s);
    bulk_g2s(d + 2 * TA,   Bbh + (size_t)c * TBB, TBB, sb + 16 * s);
    bulk_g2s(d + 2*TA+TBB, Bbl + (size_t)c * TBB, TBB, sb + 16 * s);
}

__device__ __forceinline__ void gemm_core(
        const char* __restrict__ Abh, const char* __restrict__ Abl,
        const char* __restrict__ Bbh, const char* __restrict__ Bbl,
        int kch, uint32_t sb, uint32_t st0, float acc[4][4][4]) {
    const int tid = threadIdx.x, lane = tid & 31, wid = tid >> 5;
    const int wm = wid >> 2, wn = wid & 3;

    if (tid == 0) {
        for (int s = 0; s < STAGES; ++s) {
            MBARRIER_INIT(sb + 16 * s, 1);       // full: tx-count
            MBARRIER_INIT(sb + 16 * s + 8, 8);   // empty: 8 warp arrivals
        }
    }
    __syncthreads();

    if (tid == 0) {
        int np = STAGES < kch ? STAGES : kch;
        for (int s = 0; s < np; ++s) refill(st0, sb, s, Abh, Abl, Bbh, Bbl, s);
    }

#pragma unroll
    for (int i = 0; i < 4; i++)
#pragma unroll
        for (int j = 0; j < 4; j++)
#pragma unroll
            for (int r = 0; r < 4; r++) acc[i][j][r] = 0.0f;

    const uint32_t arow = (uint32_t)wm * 5120 + (uint32_t)(lane & 15) * 80 + (uint32_t)(lane >> 4) * 16;
    const uint32_t brow = (uint32_t)(lane & 15) * 272 + (uint32_t)wn * 64 + (uint32_t)(lane >> 4) * 16;

    int s = 0, pf = 0;
    for (int c = 0; c < kch; ++c) {
        MBARRIER_WAIT_PARITY(sb + 16 * s, pf);
        uint32_t sa = st0 + s * STG;
#pragma unroll
        for (int k16 = 0; k16 < 2; ++k16) {
            uint32_t bb = sa + 2 * TA + brow + k16 * 4352;
            uint32_t bh[4][2], bl4[4][2], t[4];
            ldsm4t(t, bb);            bh[0][0]=t[0]; bh[0][1]=t[1]; bh[1][0]=t[2]; bh[1][1]=t[3];
            ldsm4t(t, bb + 32);       bh[2][0]=t[0]; bh[2][1]=t[1]; bh[3][0]=t[2]; bh[3][1]=t[3];
            ldsm4t(t, bb + TBB);      bl4[0][0]=t[0]; bl4[0][1]=t[1]; bl4[1][0]=t[2]; bl4[1][1]=t[3];
            ldsm4t(t, bb + TBB + 32); bl4[2][0]=t[0]; bl4[2][1]=t[1]; bl4[3][0]=t[2]; bl4[3][1]=t[3];
            uint32_t ab = sa + arow + k16 * 32;
#pragma unroll
            for (int mf = 0; mf < 4; ++mf) {
                uint32_t ah[4], al4[4];
                ldsm4(ah, ab + mf * 1280);
                ldsm4(al4, ab + TA + mf * 1280);
#pragma unroll
                for (int nf = 0; nf < 4; ++nf) {
                    mma16816(acc[mf][nf], ah, bh[nf]);
                    mma16816(acc[mf][nf], al4, bh[nf]);
                    mma16816(acc[mf][nf], ah, bl4[nf]);
                }
            }
        }
        // release this stage (no CTA-wide rendezvous)
        if (lane == 0) MBARRIER_ARRIVE(sb + 16 * s + 8);
        if (tid == 0 && c + STAGES < kch) {
            MBARRIER_WAIT_PARITY(sb + 16 * s + 8, pf);
            refill(st0, sb, s, Abh, Abl, Bbh, Bbl, c + STAGES);
        }
        if (++s == STAGES) { s = 0; pf ^= 1; }
    }
    __syncthreads();   // drain: all arrives landed, smem free for staging / next init
}

// ---------------- epilogue helpers ----------------
__device__ __forceinline__ void epi_alayout(float acc[4][4][4], char* outH, char* outL,
                                            size_t mtile_base) {
    const int lane = threadIdx.x & 31, wid = threadIdx.x >> 5;
    const int wm = wid >> 2, wn = wid & 3;
    const int g = lane >> 2, tg = lane & 3;
    size_t mtile = (mtile_base + wn) * TA;
#pragma unroll
    for (int mf = 0; mf < 4; ++mf)
#pragma unroll
        for (int nf = 0; nf < 4; ++nf)
#pragma unroll
            for (int rh = 0; rh < 2; ++rh) {
                int row = wm * 64 + mf * 16 + g + rh * 8;
                uint32_t hw, lw;
                split2(acc[mf][nf][rh * 2], acc[mf][nf][rh * 2 + 1], hw, lw);
                uint32_t off = (uint32_t)row * 80 + (nf * 8 + tg * 2) * 2;
                *reinterpret_cast<uint32_t*>(outH + mtile + off) = hw;
                *reinterpret_cast<uint32_t*>(outL + mtile + off) = lw;
            }
}
__device__ __forceinline__ void epi_blayout(float acc[4][4][4], char* outH, char* outL,
                                            size_t nkbase, int m0) {
    const int lane = threadIdx.x & 31, wid = threadIdx.x >> 5;
    const int wm = wid >> 2, wn = wid & 3;
    const int g = lane >> 2, tg = lane & 3;
#pragma unroll
    for (int mf = 0; mf < 4; ++mf)
#pragma unroll
        for (int rh = 0; rh < 2; ++rh) {
            int row = wm * 64 + mf * 16 + g + rh * 8;
            int kloc = m0 + row;
            size_t tile = (nkbase + (kloc >> 5)) * TBB;
            uint32_t rowoff = (uint32_t)(kloc & 31) * 272;
#pragma unroll
            for (int nf = 0; nf < 4; ++nf) {
                uint32_t hw, lw;
                split2(acc[mf][nf][rh * 2], acc[mf][nf][rh * 2 + 1], hw, lw);
                uint32_t off = rowoff + (wn * 32 + nf * 8 + tg * 2) * 2;
                *reinterpret_cast<uint32_t*>(outH + tile + off) = hw;
                *reinterpret_cast<uint32_t*>(outL + tile + off) = lw;
            }
        }
}

// ---------------- GEMM kernels ----------------
// pk3T = (swish(mask*(k@Wk)) * mask)^T  -> transposed A-layout per batch
__global__ void __launch_bounds__(256, 2)
projk_gemm(const float* __restrict__ mask) {
    extern __shared__ __align__(1024) char smem[];
    uint32_t sb = s2u(smem), st0 = sb + 1024;
    const int tid = threadIdx.x, lane = tid & 31, wid = tid >> 5;
    const int wm = wid >> 2, wn = wid & 3;
    const int bx = blockIdx.x, by = blockIdx.y;
    const int m0 = by * 128;
    const int g = lane >> 2, tg = lane & 3;

    float acc[4][4][4];
    gemm_core(g_kh + (size_t)by * 32 * TA, g_kl + (size_t)by * 32 * TA,
              g_wkh + (size_t)bx * 32 * TBB, g_wkl + (size_t)bx * 32 * TBB,
              32, sb, st0, acc);

    uint32_t shh = st0, sll = st0 + 34816;
#pragma unroll
    for (int mf = 0; mf < 4; ++mf)
#pragma unroll
        for (int rh = 0; rh < 2; ++rh) {
            int row = wm * 64 + mf * 16 + g + rh * 8;
            float mv = mask[m0 + row];
#pragma unroll
            for (int nf = 0; nf < 4; ++nf) {
                float v0 = acc[mf][nf][rh * 2] * mv;
                float v1 = acc[mf][nf][rh * 2 + 1] * mv;
                v0 = v0 / (1.0f + __expf(-v0)) * mv;   // swish, then fold pv's mask
                v1 = v1 / (1.0f + __expf(-v1)) * mv;
                uint32_t hw, lw;
                split2(v0, v1, hw, lw);
                uint32_t a = (uint32_t)row * 272 + (wn * 32 + nf * 8 + tg * 2) * 2;
                asm volatile("st.shared.b32 [%0], %1;" :: "r"(shh + a), "r"(hw) : "memory");
                asm volatile("st.shared.b32 [%0], %1;" :: "r"(sll + a), "r"(lw) : "memory");
            }
        }
    __syncthreads();
    int u = tid & 127;
    int sh2 = (tid >> 7) * 64;
    int bt = by >> 5;
    int kc0 = (m0 & 4095) >> 5;
#pragma unroll
    for (int c8 = 0; c8 < 8; ++c8) {
        int s0 = sh2 + c8 * 8;
        uint32_t hw[4], lw[4];
#pragma unroll
        for (int p = 0; p < 4; ++p) {
            unsigned short h0, h1, l0, l1;
            uint32_t a0 = (uint32_t)(s0 + 2 * p) * 272 + (uint32_t)u * 2;
            uint32_t a1 = a0 + 272;
            asm volatile("ld.shared.b16 %0, [%1];" : "=h"(h0) : "r"(shh + a0));
            asm volatile("ld.shared.b16 %0, [%1];" : "=h"(h1) : "r"(shh + a1));
            asm volatile("ld.shared.b16 %0, [%1];" : "=h"(l0) : "r"(sll + a0));
            asm volatile("ld.shared.b16 %0, [%1];" : "=h"(l1) : "r"(sll + a1));
            hw[p] = (uint32_t)h0 | ((uint32_t)h1 << 16);
            lw[p] = (uint32_t)l0 | ((uint32_t)l1 << 16);
        }
        size_t tile = ((size_t)(bt * 8 + bx) * 128 + kc0 + (s0 >> 5)) * TA;
        uint32_t off = (uint32_t)u * 80 + (s0 & 31) * 2;
        *reinterpret_cast<uint4*>(g_pkth + tile + off) = make_uint4(hw[0], hw[1], hw[2], hw[3]);
        *reinterpret_cast<uint4*>(g_pktl + tile + off) = make_uint4(lw[0], lw[1], lw[2], lw[3]);
    }
}

// WvWo = Wv @ Wo  -> B-layout (single)
__global__ void __launch_bounds__(256, 2)
wvwo_gemm() {
    extern __shared__ __align__(1024) char smem[];
    uint32_t sb = s2u(smem), st0 = sb + 1024;
    const int bx = blockIdx.x, by = blockIdx.y;
    float acc[4][4][4];
    gemm_core(g_wvh + (size_t)by * 32 * TA, g_wvl + (size_t)by * 32 * TA,
              g_woh + (size_t)bx * 32 * TBB, g_wol + (size_t)bx * 32 * TBB,
              32, sb, st0, acc);
    epi_blayout(acc, g_wvwoh, g_wvwol, (size_t)bx * 32, by * 128);
}

// kvr[b] = pk3T[b] @ v[b]  (M=1024,N=1024,K=4096) -> A-layout per batch
__global__ void __launch_bounds__(256, 2)
kvr_gemm() {
    extern __shared__ __align__(1024) char smem[];
    uint32_t sb = s2u(smem), st0 = sb + 1024;
    const int bx = blockIdx.x, by = blockIdx.y, z = blockIdx.z;
    float acc[4][4][4];
    gemm_core(g_pkth + (size_t)(z * 8 + by) * 128 * TA, g_pktl + (size_t)(z * 8 + by) * 128 * TA,
              g_vbh + (size_t)(z * 8 + bx) * 128 * TBB, g_vbl + (size_t)(z * 8 + bx) * 128 * TBB,
              128, sb, st0, acc);
    epi_alayout(acc, g_kvrh, g_kvrl, (size_t)(z * 8 + by) * 32 + bx * 4);
}

// kvo[b] = kvr[b] @ WvWo  (1024^3) -> B-layout per batch
__global__ void __launch_bounds__(256, 2)
kvo_gemm() {
    extern __shared__ __align__(1024) char smem[];
    uint32_t sb = s2u(smem), st0 = sb + 1024;
    const int bx = blockIdx.x, by = blockIdx.y, z = blockIdx.z;
    float acc[4][4][4];
    gemm_core(g_kvrh + (size_t)(z * 8 + by) * 32 * TA, g_kvrl + (size_t)(z * 8 + by) * 32 * TA,
              g_wvwoh + (size_t)bx * 32 * TBB, g_wvwol + (size_t)bx * 32 * TBB,
              32, sb, st0, acc);
    epi_blayout(acc, g_kvoh, g_kvol, (size_t)(z * 8 + bx) * 32, by * 128);
}

// fin[b] = Wq @ kvo[b]  (1024^3) -> B-layout per batch
__global__ void __launch_bounds__(256, 2)
wqkvo_gemm() {
    extern __shared__ __align__(1024) char smem[];
    uint32_t sb = s2u(smem), st0 = sb + 1024;
    const int bx = blockIdx.x, by = blockIdx.y, z = blockIdx.z;
    float acc[4][4][4];
    gemm_core(g_wqh + (size_t)by * 32 * TA, g_wql + (size_t)by * 32 * TA,
              g_kvoh + (size_t)(z * 8 + bx) * 32 * TBB, g_kvol + (size_t)(z * 8 + bx) * 32 * TBB,
              32, sb, st0, acc);
    epi_blayout(acc, g_finh, g_finl, (size_t)(z * 8 + bx) * 32, by * 128);
}

// out = q @ fin  (per batch, M=4096,N=1024,K=1024) -> f32
__global__ void __launch_bounds__(256, 2)
final_gemm(float* __restrict__ outF) {
    extern __shared__ __align__(1024) char smem[];
    uint32_t sb = s2u(smem), st0 = sb + 1024;
    const int tid = threadIdx.x, lane = tid & 31, wid = tid >> 5;
    const int wm = wid >> 2, wn = wid & 3;
    const int bx = blockIdx.x, by = blockIdx.y, z = blockIdx.z;
    const int g = lane >> 2, tg = lane & 3;
    const int mb = z * 32 + by;
    const int n0 = bx * 128;

    float acc[4][4][4];
    gemm_core(g_qh + (size_t)mb * 32 * TA, g_ql + (size_t)mb * 32 * TA,
              g_finh + (size_t)(z * 8 + bx) * 32 * TBB, g_finl + (size_t)(z * 8 + bx) * 32 * TBB,
              32, sb, st0, acc);

#pragma unroll
    for (int mf = 0; mf < 4; ++mf)
#pragma unroll
        for (int nf = 0; nf < 4; ++nf)
#pragma unroll
            for (int rh = 0; rh < 2; ++rh) {
                int row = wm * 64 + mf * 16 + g + rh * 8;
                int gcol = n0 + wn * 32 + nf * 8 + tg * 2;
                float2 v = make_float2(acc[mf][nf][rh * 2], acc[mf][nf][rh * 2 + 1]);
                *reinterpret_cast<float2*>(outF + ((size_t)mb * 128 + row) * 1024 + gcol) = v;
            }
}

// ---------------- launch ----------------
extern "C" void kernel_launch(void* const* d_in, const int* in_sizes, int n_in,
                              void* d_out, int out_size) {
    const float* query = (const float*)d_in[0];
    const float* key   = (const float*)d_in[1];
    const float* value = (const float*)d_in[2];
    const float* mask  = (const float*)d_in[3];
    const float* Wk    = (const float*)d_in[4];
    const float* Wv    = (const float*)d_in[5];
    const float* Wq    = (const float*)d_in[6];
    const float* Wo    = (const float*)d_in[7];
    float* out = (float*)d_out;

    static bool attr_done = false;
    if (!attr_done) {
        cudaFuncSetAttribute(projk_gemm, cudaFuncAttributeMaxDynamicSharedMemorySize, SMEM_SZ);
        cudaFuncSetAttribute(wvwo_gemm,  cudaFuncAttributeMaxDynamicSharedMemorySize, SMEM_SZ);
        cudaFuncSetAttribute(kvr_gemm,   cudaFuncAttributeMaxDynamicSharedMemorySize, SMEM_SZ);
        cudaFuncSetAttribute(kvo_gemm,   cudaFuncAttributeMaxDynamicSharedMemorySize, SMEM_SZ);
        cudaFuncSetAttribute(wqkvo_gemm, cudaFuncAttributeMaxDynamicSharedMemorySize, SMEM_SZ);
        cudaFuncSetAttribute(final_gemm, cudaFuncAttributeMaxDynamicSharedMemorySize, SMEM_SZ);
        attr_done = true;
    }

    conv_acts<<<dim3(8192, 3), 256>>>(query, key, value);
    conv_ws<<<dim3(512, 4), 256>>>(Wk, Wo, Wq, Wv);

    wvwo_gemm<<<dim3(8, 8, 1), 256, SMEM_SZ>>>();
    projk_gemm<<<dim3(8, 128, 1), 256, SMEM_SZ>>>(mask);
    kvr_gemm<<<dim3(8, 8, 4), 256, SMEM_SZ>>>();
    kvo_gemm<<<dim3(8, 8, 4), 256, SMEM_SZ>>>();
    wqkvo_gemm<<<dim3(8, 8, 4), 256, SMEM_SZ>>>();
    final_gemm<<<dim3(8, 32, 4), 256, SMEM_SZ>>>(out);
}

// round 9
// speedup vs baseline: 5.0195x; 1.0261x over previous
#include <cuda_runtime.h>
#include <cuda_bf16.h>
#include <cstdint>
#include <string.h>
#include <math.h>

typedef __nv_bfloat16 bf16;

// A tile: 128 logical rows x 32 bf16, packed as [64 phys rows][128B], chunk^=(p&7) swizzle. 8192B.
// B tile: 32 k-rows x 128 bf16, as 2 n-halves of [32 rows][128B], chunk^=(r&7) swizzle. 8192B.
#define TA 8192
#define TBB 8192
#define STG (2*TA + 2*TBB)     // 32768 per stage (Ah, Al, Bh, Bl)
#define STAGES 3
#define SMEM_SZ (1024 + STAGES*STG)   // 99328 -> 2 CTAs/SM

// ---------------- device-global scratch ----------------
__device__ __align__(128) char g_qh[128*32*TA], g_ql[128*32*TA];       // q  A-layout
__device__ __align__(128) char g_kh[128*32*TA], g_kl[128*32*TA];       // k  A-layout
__device__ __align__(128) char g_vbh[4*8*128*TBB], g_vbl[4*8*128*TBB]; // v  B-layout per batch
__device__ __align__(128) char g_wkh[8*32*TBB], g_wkl[8*32*TBB];       // Wk B-layout
__device__ __align__(128) char g_woh[8*32*TBB], g_wol[8*32*TBB];       // Wo B-layout
__device__ __align__(128) char g_wqh[8*32*TA],  g_wql[8*32*TA];        // Wq A-layout
__device__ __align__(128) char g_wvh[8*32*TA],  g_wvl[8*32*TA];        // Wv A-layout
__device__ __align__(128) char g_pkth[4*8*128*TA], g_pktl[4*8*128*TA]; // (swish(mask*kWk)*mask)^T A-layout
__device__ __align__(128) char g_wvwoh[8*32*TBB], g_wvwol[8*32*TBB];   // Wv@Wo B-layout
__device__ __align__(128) char g_kvrh[4*8*32*TA], g_kvrl[4*8*32*TA];   // pk3T@v A-layout per batch
__device__ __align__(128) char g_kvoh[4*8*32*TBB], g_kvol[4*8*32*TBB]; // kvr@WvWo B-layout per batch
__device__ __align__(128) char g_finh[4*8*32*TBB], g_finl[4*8*32*TBB]; // Wq@kvo B-layout per batch

// ---------------- PTX helpers ----------------
__device__ __forceinline__ uint32_t s2u(const void* p) {
    uint32_t a;
    asm("{ .reg .u64 t; cvta.to.shared.u64 t, %1; cvt.u32.u64 %0, t; }" : "=r"(a) : "l"(p));
    return a;
}
#define MBARRIER_INIT(addr, cnt) \
    asm volatile("mbarrier.init.shared.b64 [%0], %1;" :: "r"((uint32_t)(addr)), "r"((uint32_t)(cnt)) : "memory")
#define MBARRIER_EXPECT_TX(addr, bytes) \
    asm volatile("mbarrier.arrive.expect_tx.shared.b64 _, [%0], %1;" :: "r"((uint32_t)(addr)), "r"((uint32_t)(bytes)) : "memory")
#define MBARRIER_WAIT_PARITY(mbar, par) do { \
    uint32_t _m = (uint32_t)(mbar); uint32_t _p = (uint32_t)(par); uint32_t _d; \
    asm volatile("{\n\t.reg .pred p;\n\tmbarrier.try_wait.parity.acquire.cta.shared::cta.b64 p, [%1], %2;\n\tselp.b32 %0, 1, 0, p;\n\t}" \
        : "=r"(_d) : "r"(_m), "r"(_p) : "memory"); \
    if (!_d) { \
        asm volatile("{\n\t.reg .pred P1;\n\tWL_%=:\n\tmbarrier.try_wait.parity.acquire.cta.shared::cta.b64 P1, [%0], %1, 0x989680;\n\t@P1 bra.uni WD_%=;\n\tbra.uni WL_%=;\n\tWD_%=:\n\t}" \
            :: "r"(_m), "r"(_p) : "memory"); \
    } \
} while(0)

__device__ __forceinline__ void bulk_g2s(uint32_t dst, const void* src, uint32_t bytes, uint32_t mbar) {
    asm volatile("cp.async.bulk.shared::cluster.global.mbarrier::complete_tx::bytes [%0], [%1], %2, [%3];"
        :: "r"(dst), "l"(src), "r"(bytes), "r"(mbar) : "memory");
}
__device__ __forceinline__ void ldsm4(uint32_t* r, uint32_t a) {
    asm volatile("ldmatrix.sync.aligned.m8n8.x4.shared.b16 {%0,%1,%2,%3}, [%4];"
        : "=r"(r[0]), "=r"(r[1]), "=r"(r[2]), "=r"(r[3]) : "r"(a));
}
__device__ __forceinline__ void ldsm4t(uint32_t* r, uint32_t a) {
    asm volatile("ldmatrix.sync.aligned.m8n8.x4.trans.shared.b16 {%0,%1,%2,%3}, [%4];"
        : "=r"(r[0]), "=r"(r[1]), "=r"(r[2]), "=r"(r[3]) : "r"(a));
}
__device__ __forceinline__ void mma16816(float* c, const uint32_t* a, const uint32_t* b) {
    asm volatile("mma.sync.aligned.m16n8k16.row.col.f32.bf16.bf16.f32 "
        "{%0,%1,%2,%3}, {%4,%5,%6,%7}, {%8,%9}, {%0,%1,%2,%3};"
        : "+f"(c[0]), "+f"(c[1]), "+f"(c[2]), "+f"(c[3])
        : "r"(a[0]), "r"(a[1]), "r"(a[2]), "r"(a[3]), "r"(b[0]), "r"(b[1]));
}

__device__ __forceinline__ unsigned short bfraw(bf16 h) { unsigned short u; memcpy(&u, &h, 2); return u; }
__device__ __forceinline__ void split2(float x, float y, uint32_t& H, uint32_t& L) {
    bf16 hx = __float2bfloat16(x), hy = __float2bfloat16(y);
    bf16 lx = __float2bfloat16(x - __bfloat162float(hx));
    bf16 ly = __float2bfloat16(y - __bfloat162float(hy));
    H = (uint32_t)bfraw(hx) | ((uint32_t)bfraw(hy) << 16);
    L = (uint32_t)bfraw(lx) | ((uint32_t)bfraw(ly) << 16);
}

// swizzled in-tile offsets (16B chunk granular)
__device__ __forceinline__ uint32_t a_off(int row, int kbyte) {   // row 0..127, kbyte 0..63
    int p = row >> 1;
    int c = (row & 1) * 4 + (kbyte >> 4);
    return (uint32_t)p * 128 + (uint32_t)((c ^ (p & 7)) * 16) + (kbyte & 15);
}
__device__ __forceinline__ uint32_t b_off(int r, int nbyte) {     // r 0..31, nbyte 0..255
    int q = nbyte >> 7;
    int c = (nbyte & 127) >> 4;
    return (uint32_t)q * 4096 + (uint32_t)r * 128 + (uint32_t)((c ^ (r & 7)) * 16) + (nbyte & 15);
}

// ---------------- conversions ----------------
// z=0: q -> A-layout; z=1: k -> A-layout; z=2: v -> B-layout per batch
__global__ void conv_acts(const float* __restrict__ q, const float* __restrict__ k,
                          const float* __restrict__ v) {
    int zz = blockIdx.y;
    const float* src = zz == 0 ? q : zz == 1 ? k : v;
    int idx = blockIdx.x * 256 + threadIdx.x;   // 16384*128
    int m = idx >> 7;
    int u0 = (idx & 127) << 3;
    const float4* s = reinterpret_cast<const float4*>(src + ((size_t)m << 10) + u0);
    float4 a = s[0], b = s[1];
    uint32_t h[4], l[4];
    split2(a.x, a.y, h[0], l[0]); split2(a.z, a.w, h[1], l[1]);
    split2(b.x, b.y, h[2], l[2]); split2(b.z, b.w, h[3], l[3]);
    if (zz < 2) {
        char* hi = zz == 0 ? g_qh : g_kh;
        char* lo = zz == 0 ? g_ql : g_kl;
        size_t tile = ((size_t)(m >> 7) * 32 + (u0 >> 5)) * TA;
        uint32_t off = a_off(m & 127, (u0 & 31) * 2);
        *reinterpret_cast<uint4*>(hi + tile + off) = make_uint4(h[0], h[1], h[2], h[3]);
        *reinterpret_cast<uint4*>(lo + tile + off) = make_uint4(l[0], l[1], l[2], l[3]);
    } else {
        int batch = m >> 12, sloc = m & 4095;
        size_t tile = ((size_t)(batch * 8 + (u0 >> 7)) * 128 + (sloc >> 5)) * TBB;
        uint32_t off = b_off(sloc & 31, (u0 & 127) * 2);
        *reinterpret_cast<uint4*>(g_vbh + tile + off) = make_uint4(h[0], h[1], h[2], h[3]);
        *reinterpret_cast<uint4*>(g_vbl + tile + off) = make_uint4(l[0], l[1], l[2], l[3]);
    }
}
// z=0: Wk B-layout; z=1: Wo B-layout; z=2: Wq A-layout; z=3: Wv A-layout
__global__ void conv_ws(const float* __restrict__ Wk, const float* __restrict__ Wo,
                        const float* __restrict__ Wq, const float* __restrict__ Wv) {
    int zz = blockIdx.y;
    const float* W = zz == 0 ? Wk : zz == 1 ? Wo : zz == 2 ? Wq : Wv;
    int idx = blockIdx.x * 256 + threadIdx.x;   // 1024*128
    int r = idx >> 7;
    int c0 = (idx & 127) << 3;
    const float4* s = reinterpret_cast<const float4*>(W + ((size_t)r << 10) + c0);
    float4 a = s[0], b = s[1];
    uint32_t h[4], l[4];
    split2(a.x, a.y, h[0], l[0]); split2(a.z, a.w, h[1], l[1]);
    split2(b.x, b.y, h[2], l[2]); split2(b.z, b.w, h[3], l[3]);
    if (zz < 2) {
        char* hi = zz == 0 ? g_wkh : g_woh;
        char* lo = zz == 0 ? g_wkl : g_wol;
        size_t tile = ((size_t)(c0 >> 7) * 32 + (r >> 5)) * TBB;
        uint32_t off = b_off(r & 31, (c0 & 127) * 2);
        *reinterpret_cast<uint4*>(hi + tile + off) = make_uint4(h[0], h[1], h[2], h[3]);
        *reinterpret_cast<uint4*>(lo + tile + off) = make_uint4(l[0], l[1], l[2], l[3]);
    } else {
        char* hi = zz == 2 ? g_wqh : g_wvh;
        char* lo = zz == 2 ? g_wql : g_wvl;
        size_t tile = ((size_t)(r >> 7) * 32 + (c0 >> 5)) * TA;
        uint32_t off = a_off(r & 127, (c0 & 31) * 2);
        *reinterpret_cast<uint4*>(hi + tile + off) = make_uint4(h[0], h[1], h[2], h[3]);
        *reinterpret_cast<uint4*>(lo + tile + off) = make_uint4(l[0], l[1], l[2], l[3]);
    }
}

// ---------------- shared GEMM mainloop ----------------
__device__ __forceinline__ void refill(uint32_t st0, uint32_t sb, int s,
        const char* Abh, const char* Abl, const char* Bbh, const char* Bbl, int c) {
    MBARRIER_EXPECT_TX(sb + 8 * s, STG);
    uint32_t d = st0 + s * STG;
    bulk_g2s(d,            Abh + (size_t)c * TA,  TA,  sb + 8 * s);
    bulk_g2s(d + TA,       Abl + (size_t)c * TA,  TA,  sb + 8 * s);
    bulk_g2s(d + 2 * TA,   Bbh + (size_t)c * TBB, TBB, sb + 8 * s);
    bulk_g2s(d + 2*TA+TBB, Bbl + (size_t)c * TBB, TBB, sb + 8 * s);
}

__device__ __forceinline__ void gemm_core(
        const char* __restrict__ Abh, const char* __restrict__ Abl,
        const char* __restrict__ Bbh, const char* __restrict__ Bbl,
        int kch, uint32_t sb, uint32_t st0, float acc[4][4][4]) {
    const int tid = threadIdx.x, lane = tid & 31, wid = tid >> 5;
    const int wm = wid >> 2, wn = wid & 3;
    const int i = lane & 15, h = lane >> 4;

    if (tid == 0)
        for (int s = 0; s < STAGES; ++s) MBARRIER_INIT(sb + 8 * s, 1);
    __syncthreads();

    if (tid == 0) {
        int np = STAGES < kch ? STAGES : kch;
        for (int s = 0; s < np; ++s) refill(st0, sb, s, Abh, Abl, Bbh, Bbl, s);
    }

#pragma unroll
    for (int ii = 0; ii < 4; ii++)
#pragma unroll
        for (int j = 0; j < 4; j++)
#pragma unroll
            for (int r = 0; r < 4; r++) acc[ii][j][r] = 0.0f;

    // A: lane (i,h) -> phys row p = base + (i>>1), chunk c = (i&1)*4 + k16*2 + h, xor (p&7)=(i>>1)&7
    const uint32_t aBase = (uint32_t)wm * 4096 + (uint32_t)(i >> 1) * 128;
    const int xA = (i >> 1) & 7;
    const int cA0 = (i & 1) * 4 + h;
    // B: row r = i + k16*16, xor r&7 = lane&7 (const); chunk C = (wn&1)*4 + h + 2j
    const uint32_t qOff = (uint32_t)(wn >> 1) * 4096;
    const int xB = lane & 7;
    const uint32_t pj0 = (uint32_t)((((wn & 1) * 4 + h)     ^ xB) * 16);
    const uint32_t pj1 = (uint32_t)((((wn & 1) * 4 + h + 2) ^ xB) * 16);
    const uint32_t bRow = (uint32_t)i * 128;

    int s = 0, pf = 0;
    for (int c = 0; c < kch; ++c) {
        MBARRIER_WAIT_PARITY(sb + 8 * s, pf);
        uint32_t sa = st0 + s * STG;
#pragma unroll
        for (int k16 = 0; k16 < 2; ++k16) {
            uint32_t bb = sa + 2 * TA + qOff + bRow + k16 * 2048;
            uint32_t bh[4][2], bl4[4][2], t[4];
            ldsm4t(t, bb + pj0);        bh[0][0]=t[0]; bh[0][1]=t[1]; bh[1][0]=t[2]; bh[1][1]=t[3];
            ldsm4t(t, bb + pj1);        bh[2][0]=t[0]; bh[2][1]=t[1]; bh[3][0]=t[2]; bh[3][1]=t[3];
            ldsm4t(t, bb + TBB + pj0);  bl4[0][0]=t[0]; bl4[0][1]=t[1]; bl4[1][0]=t[2]; bl4[1][1]=t[3];
            ldsm4t(t, bb + TBB + pj1);  bl4[2][0]=t[0]; bl4[2][1]=t[1]; bl4[3][0]=t[2]; bl4[3][1]=t[3];
            uint32_t aoff = (uint32_t)(((cA0 + k16 * 2) ^ xA) * 16);
            uint32_t ab = sa + aBase + aoff;
#pragma unroll
            for (int mf = 0; mf < 4; ++mf) {
                uint32_t ah[4], al4[4];
                ldsm4(ah, ab + mf * 1024);
                ldsm4(al4, ab + TA + mf * 1024);
#pragma unroll
                for (int nf = 0; nf < 4; ++nf) {
                    mma16816(acc[mf][nf], ah, bh[nf]);
                    mma16816(acc[mf][nf], al4, bh[nf]);
                    mma16816(acc[mf][nf], ah, bl4[nf]);
                }
            }
        }
        __syncthreads();
        if (tid == 0 && c + STAGES < kch)
            refill(st0, sb, s, Abh, Abl, Bbh, Bbl, c + STAGES);
        if (++s == STAGES) { s = 0; pf ^= 1; }
    }
}

// ---------------- epilogue helpers ----------------
__device__ __forceinline__ void epi_alayout(float acc[4][4][4], char* outH, char* outL,
                                            size_t mtile_base) {
    const int lane = threadIdx.x & 31, wid = threadIdx.x >> 5;
    const int wm = wid >> 2, wn = wid & 3;
    const int g = lane >> 2, tg = lane & 3;
    size_t mtile = (mtile_base + wn) * TA;
#pragma unroll
    for (int mf = 0; mf < 4; ++mf)
#pragma unroll
        for (int nf = 0; nf < 4; ++nf)
#pragma unroll
            for (int rh = 0; rh < 2; ++rh) {
                int row = wm * 64 + mf * 16 + g + rh * 8;
                uint32_t hw, lw;
                split2(acc[mf][nf][rh * 2], acc[mf][nf][rh * 2 + 1], hw, lw);
                uint32_t off = a_off(row, nf * 16 + tg * 4);
                *reinterpret_cast<uint32_t*>(outH + mtile + off) = hw;
                *reinterpret_cast<uint32_t*>(outL + mtile + off) = lw;
            }
}
__device__ __forceinline__ void epi_blayout(float acc[4][4][4], char* outH, char* outL,
                                            size_t nkbase, int m0) {
    const int lane = threadIdx.x & 31, wid = threadIdx.x >> 5;
    const int wm = wid >> 2, wn = wid & 3;
    const int g = lane >> 2, tg = lane & 3;
#pragma unroll
    for (int mf = 0; mf < 4; ++mf)
#pragma unroll
        for (int rh = 0; rh < 2; ++rh) {
            int row = wm * 64 + mf * 16 + g + rh * 8;
            int kloc = m0 + row;
            size_t tile = (nkbase + (kloc >> 5)) * TBB;
#pragma unroll
            for (int nf = 0; nf < 4; ++nf) {
                uint32_t hw, lw;
                split2(acc[mf][nf][rh * 2], acc[mf][nf][rh * 2 + 1], hw, lw);
                uint32_t off = b_off(kloc & 31, (wn * 32 + nf * 8 + tg * 2) * 2);
                *reinterpret_cast<uint32_t*>(outH + tile + off) = hw;
                *reinterpret_cast<uint32_t*>(outL + tile + off) = lw;
            }
        }
}

// ---------------- GEMM kernels ----------------
// pk3T = (swish(mask*(k@Wk)) * mask)^T  -> transposed A-layout per batch
__global__ void __launch_bounds__(256, 2)
projk_gemm(const float* __restrict__ mask) {
    extern __shared__ __align__(1024) char smem[];
    uint32_t sb = s2u(smem), st0 = sb + 1024;
    const int tid = threadIdx.x, lane = tid & 31, wid = tid >> 5;
    const int wm = wid >> 2, wn = wid & 3;
    const int bx = blockIdx.x, by = blockIdx.y;
    const int m0 = by * 128;
    const int g = lane >> 2, tg = lane & 3;

    float acc[4][4][4];
    gemm_core(g_kh + (size_t)by * 32 * TA, g_kl + (size_t)by * 32 * TA,
              g_wkh + (size_t)bx * 32 * TBB, g_wkl + (size_t)bx * 32 * TBB,
              32, sb, st0, acc);
    __syncthreads();   // stage smem reuse below

    uint32_t shh = st0, sll = st0 + 34816;
#pragma unroll
    for (int mf = 0; mf < 4; ++mf)
#pragma unroll
        for (int rh = 0; rh < 2; ++rh) {
            int row = wm * 64 + mf * 16 + g + rh * 8;
            float mv = mask[m0 + row];
#pragma unroll
            for (int nf = 0; nf < 4; ++nf) {
                float v0 = acc[mf][nf][rh * 2] * mv;
                float v1 = acc[mf][nf][rh * 2 + 1] * mv;
                v0 = v0 / (1.0f + __expf(-v0)) * mv;   // swish, then fold pv's mask
                v1 = v1 / (1.0f + __expf(-v1)) * mv;
                uint32_t hw, lw;
                split2(v0, v1, hw, lw);
                uint32_t a = (uint32_t)row * 272 + (wn * 32 + nf * 8 + tg * 2) * 2;
                asm volatile("st.shared.b32 [%0], %1;" :: "r"(shh + a), "r"(hw) : "memory");
                asm volatile("st.shared.b32 [%0], %1;" :: "r"(sll + a), "r"(lw) : "memory");
            }
        }
    __syncthreads();
    int u = tid & 127;
    int sh2 = (tid >> 7) * 64;
    int bt = by >> 5;
    int kc0 = (m0 & 4095) >> 5;
#pragma unroll
    for (int c8 = 0; c8 < 8; ++c8) {
        int s0 = sh2 + c8 * 8;
        uint32_t hw[4], lw[4];
#pragma unroll
        for (int p = 0; p < 4; ++p) {
            unsigned short h0, h1, l0, l1;
            uint32_t a0 = (uint32_t)(s0 + 2 * p) * 272 + (uint32_t)u * 2;
            uint32_t a1 = a0 + 272;
            asm volatile("ld.shared.b16 %0, [%1];" : "=h"(h0) : "r"(shh + a0));
            asm volatile("ld.shared.b16 %0, [%1];" : "=h"(h1) : "r"(shh + a1));
            asm volatile("ld.shared.b16 %0, [%1];" : "=h"(l0) : "r"(sll + a0));
            asm volatile("ld.shared.b16 %0, [%1];" : "=h"(l1) : "r"(sll + a1));
            hw[p] = (uint32_t)h0 | ((uint32_t)h1 << 16);
            lw[p] = (uint32_t)l0 | ((uint32_t)l1 << 16);
        }
        size_t tile = ((size_t)(bt * 8 + bx) * 128 + kc0 + (s0 >> 5)) * TA;
        uint32_t off = a_off(u, (s0 & 31) * 2);
        *reinterpret_cast<uint4*>(g_pkth + tile + off) = make_uint4(hw[0], hw[1], hw[2], hw[3]);
        *reinterpret_cast<uint4*>(g_pktl + tile + off) = make_uint4(lw[0], lw[1], lw[2], lw[3]);
    }
}

// WvWo = Wv @ Wo  -> B-layout (single)
__global__ void __launch_bounds__(256, 2)
wvwo_gemm() {
    extern __shared__ __align__(1024) char smem[];
    uint32_t sb = s2u(smem), st0 = sb + 1024;
    const int bx = blockIdx.x, by = blockIdx.y;
    float acc[4][4][4];
    gemm_core(g_wvh + (size_t)by * 32 * TA, g_wvl + (size_t)by * 32 * TA,
              g_woh + (size_t)bx * 32 * TBB, g_wol + (size_t)bx * 32 * TBB,
              32, sb, st0, acc);
    epi_blayout(acc, g_wvwoh, g_wvwol, (size_t)bx * 32, by * 128);
}

// kvr[b] = pk3T[b] @ v[b]  (M=1024,N=1024,K=4096) -> A-layout per batch
__global__ void __launch_bounds__(256, 2)
kvr_gemm() {
    extern __shared__ __align__(1024) char smem[];
    uint32_t sb = s2u(smem), st0 = sb + 1024;
    const int bx = blockIdx.x, by = blockIdx.y, z = blockIdx.z;
    float acc[4][4][4];
    gemm_core(g_pkth + (size_t)(z * 8 + by) * 128 * TA, g_pktl + (size_t)(z * 8 + by) * 128 * TA,
              g_vbh + (size_t)(z * 8 + bx) * 128 * TBB, g_vbl + (size_t)(z * 8 + bx) * 128 * TBB,
              128, sb, st0, acc);
    epi_alayout(acc, g_kvrh, g_kvrl, (size_t)(z * 8 + by) * 32 + bx * 4);
}

// kvo[b] = kvr[b] @ WvWo  (1024^3) -> B-layout per batch
__global__ void __launch_bounds__(256, 2)
kvo_gemm() {
    extern __shared__ __align__(1024) char smem[];
    uint32_t sb = s2u(smem), st0 = sb + 1024;
    const int bx = blockIdx.x, by = blockIdx.y, z = blockIdx.z;
    float acc[4][4][4];
    gemm_core(g_kvrh + (size_t)(z * 8 + by) * 32 * TA, g_kvrl + (size_t)(z * 8 + by) * 32 * TA,
              g_wvwoh + (size_t)bx * 32 * TBB, g_wvwol + (size_t)bx * 32 * TBB,
              32, sb, st0, acc);
    epi_blayout(acc, g_kvoh, g_kvol, (size_t)(z * 8 + bx) * 32, by * 128);
}

// fin[b] = Wq @ kvo[b]  (1024^3) -> B-layout per batch
__global__ void __launch_bounds__(256, 2)
wqkvo_gemm() {
    extern __shared__ __align__(1024) char smem[];
    uint32_t sb = s2u(smem), st0 = sb + 1024;
    const int bx = blockIdx.x, by = blockIdx.y, z = blockIdx.z;
    float acc[4][4][4];
    gemm_core(g_wqh + (size_t)by * 32 * TA, g_wql + (size_t)by * 32 * TA,
              g_kvoh + (size_t)(z * 8 + bx) * 32 * TBB, g_kvol + (size_t)(z * 8 + bx) * 32 * TBB,
              32, sb, st0, acc);
    epi_blayout(acc, g_finh, g_finl, (size_t)(z * 8 + bx) * 32, by * 128);
}

// out = q @ fin  (per batch, M=4096,N=1024,K=1024) -> f32
__global__ void __launch_bounds__(256, 2)
final_gemm(float* __restrict__ outF) {
    extern __shared__ __align__(1024) char smem[];
    uint32_t sb = s2u(smem), st0 = sb + 1024;
    const int tid = threadIdx.x, lane = tid & 31, wid = tid >> 5;
    const int wm = wid >> 2, wn = wid & 3;
    const int bx = blockIdx.x, by = blockIdx.y, z = blockIdx.z;
    const int g = lane >> 2, tg = lane & 3;
    const int mb = z * 32 + by;
    const int n0 = bx * 128;

    float acc[4][4][4];
    gemm_core(g_qh + (size_t)mb * 32 * TA, g_ql + (size_t)mb * 32 * TA,
              g_finh + (size_t)(z * 8 + bx) * 32 * TBB, g_finl + (size_t)(z * 8 + bx) * 32 * TBB,
              32, sb, st0, acc);

#pragma unroll
    for (int mf = 0; mf < 4; ++mf)
#pragma unroll
        for (int nf = 0; nf < 4; ++nf)
#pragma unroll
            for (int rh = 0; rh < 2; ++rh) {
                int row = wm * 64 + mf * 16 + g + rh * 8;
                int gcol = n0 + wn * 32 + nf * 8 + tg * 2;
                float2 v = make_float2(acc[mf][nf][rh * 2], acc[mf][nf][rh * 2 + 1]);
                *reinterpret_cast<float2*>(outF + ((size_t)mb * 128 + row) * 1024 + gcol) = v;
            }
}

// ---------------- launch ----------------
extern "C" void kernel_launch(void* const* d_in, const int* in_sizes, int n_in,
                              void* d_out, int out_size) {
    const float* query = (const float*)d_in[0];
    const float* key   = (const float*)d_in[1];
    const float* value = (const float*)d_in[2];
    const float* mask  = (const float*)d_in[3];
    const float* Wk    = (const float*)d_in[4];
    const float* Wv    = (const float*)d_in[5];
    const float* Wq    = (const float*)d_in[6];
    const float* Wo    = (const float*)d_in[7];
    float* out = (float*)d_out;

    static bool attr_done = false;
    if (!attr_done) {
        cudaFuncSetAttribute(projk_gemm, cudaFuncAttributeMaxDynamicSharedMemorySize, SMEM_SZ);
        cudaFuncSetAttribute(wvwo_gemm,  cudaFuncAttributeMaxDynamicSharedMemorySize, SMEM_SZ);
        cudaFuncSetAttribute(kvr_gemm,   cudaFuncAttributeMaxDynamicSharedMemorySize, SMEM_SZ);
        cudaFuncSetAttribute(kvo_gemm,   cudaFuncAttributeMaxDynamicSharedMemorySize, SMEM_SZ);
        cudaFuncSetAttribute(wqkvo_gemm, cudaFuncAttributeMaxDynamicSharedMemorySize, SMEM_SZ);
        cudaFuncSetAttribute(final_gemm, cudaFuncAttributeMaxDynamicSharedMemorySize, SMEM_SZ);
        attr_done = true;
    }

    conv_acts<<<dim3(8192, 3), 256>>>(query, key, value);
    conv_ws<<<dim3(512, 4), 256>>>(Wk, Wo, Wq, Wv);

    wvwo_gemm<<<dim3(8, 8, 1), 256, SMEM_SZ>>>();
    projk_gemm<<<dim3(8, 128, 1), 256, SMEM_SZ>>>(mask);
    kvr_gemm<<<dim3(8, 8, 4), 256, SMEM_SZ>>>();
    kvo_gemm<<<dim3(8, 8, 4), 256, SMEM_SZ>>>();
    wqkvo_gemm<<<dim3(8, 8, 4), 256, SMEM_SZ>>>();
    final_gemm<<<dim3(8, 32, 4), 256, SMEM_SZ>>>(out);
}

// round 11
// speedup vs baseline: 5.0979x; 1.0156x over previous
#include <cuda_runtime.h>
#include <cuda_bf16.h>
#include <cstdint>
#include <string.h>
#include <math.h>

typedef __nv_bfloat16 bf16;

#define TA 8192
#define TBB 8192
#define STG (2*TA + 2*TBB)
#define STAGES 3
#define SMEM_SZ (1024 + STAGES*STG)   // 99328 -> 2 CTAs/SM

// ---------------- device-global scratch ----------------
__device__ __align__(128) char g_qh[128*32*TA], g_ql[128*32*TA];
__device__ __align__(128) char g_kh[128*32*TA], g_kl[128*32*TA];
__device__ __align__(128) char g_vbh[4*8*128*TBB], g_vbl[4*8*128*TBB];
__device__ __align__(128) char g_wkh[8*32*TBB], g_wkl[8*32*TBB];
__device__ __align__(128) char g_woh[8*32*TBB], g_wol[8*32*TBB];
__device__ __align__(128) char g_wqh[8*32*TA],  g_wql[8*32*TA];
__device__ __align__(128) char g_wvh[8*32*TA],  g_wvl[8*32*TA];
__device__ __align__(128) char g_pkth[4*8*128*TA], g_pktl[4*8*128*TA];
__device__ __align__(128) char g_wvwoh[8*32*TBB], g_wvwol[8*32*TBB];
__device__ __align__(128) char g_kvrh[4*8*32*TA], g_kvrl[4*8*32*TA];
__device__ __align__(128) char g_kvoh[4*8*32*TBB], g_kvol[4*8*32*TBB];
__device__ __align__(128) char g_finh[4*8*32*TBB], g_finl[4*8*32*TBB];
__device__ unsigned int g_barA[2];
__device__ unsigned int g_barD[2];

// ---------------- PTX helpers ----------------
__device__ __forceinline__ uint32_t s2u(const void* p) {
    uint32_t a;
    asm("{ .reg .u64 t; cvta.to.shared.u64 t, %1; cvt.u32.u64 %0, t; }" : "=r"(a) : "l"(p));
    return a;
}
#define MBARRIER_INIT(addr, cnt) \
    asm volatile("mbarrier.init.shared.b64 [%0], %1;" :: "r"((uint32_t)(addr)), "r"((uint32_t)(cnt)) : "memory")
#define MBARRIER_EXPECT_TX(addr, bytes) \
    asm volatile("mbarrier.arrive.expect_tx.shared.b64 _, [%0], %1;" :: "r"((uint32_t)(addr)), "r"((uint32_t)(bytes)) : "memory")
#define MBARRIER_WAIT_PARITY(mbar, par) do { \
    uint32_t _m = (uint32_t)(mbar); uint32_t _p = (uint32_t)(par); uint32_t _d; \
    asm volatile("{\n\t.reg .pred p;\n\tmbarrier.try_wait.parity.acquire.cta.shared::cta.b64 p, [%1], %2;\n\tselp.b32 %0, 1, 0, p;\n\t}" \
        : "=r"(_d) : "r"(_m), "r"(_p) : "memory"); \
    if (!_d) { \
        asm volatile("{\n\t.reg .pred P1;\n\tWL_%=:\n\tmbarrier.try_wait.parity.acquire.cta.shared::cta.b64 P1, [%0], %1, 0x989680;\n\t@P1 bra.uni WD_%=;\n\tbra.uni WL_%=;\n\tWD_%=:\n\t}" \
            :: "r"(_m), "r"(_p) : "memory"); \
    } \
} while(0)

__device__ __forceinline__ void bulk_g2s(uint32_t dst, const void* src, uint32_t bytes, uint32_t mbar) {
    asm volatile("cp.async.bulk.shared::cluster.global.mbarrier::complete_tx::bytes [%0], [%1], %2, [%3];"
        :: "r"(dst), "l"(src), "r"(bytes), "r"(mbar) : "memory");
}
__device__ __forceinline__ void ldsm4(uint32_t* r, uint32_t a) {
    asm volatile("ldmatrix.sync.aligned.m8n8.x4.shared.b16 {%0,%1,%2,%3}, [%4];"
        : "=r"(r[0]), "=r"(r[1]), "=r"(r[2]), "=r"(r[3]) : "r"(a));
}
__device__ __forceinline__ void ldsm4t(uint32_t* r, uint32_t a) {
    asm volatile("ldmatrix.sync.aligned.m8n8.x4.trans.shared.b16 {%0,%1,%2,%3}, [%4];"
        : "=r"(r[0]), "=r"(r[1]), "=r"(r[2]), "=r"(r[3]) : "r"(a));
}
__device__ __forceinline__ void mma16816(float* c, const uint32_t* a, const uint32_t* b) {
    asm volatile("mma.sync.aligned.m16n8k16.row.col.f32.bf16.bf16.f32 "
        "{%0,%1,%2,%3}, {%4,%5,%6,%7}, {%8,%9}, {%0,%1,%2,%3};"
        : "+f"(c[0]), "+f"(c[1]), "+f"(c[2]), "+f"(c[3])
        : "r"(a[0]), "r"(a[1]), "r"(a[2]), "r"(a[3]), "r"(b[0]), "r"(b[1]));
}

__device__ __forceinline__ unsigned short bfraw(bf16 h) { unsigned short u; memcpy(&u, &h, 2); return u; }
__device__ __forceinline__ void split2(float x, float y, uint32_t& H, uint32_t& L) {
    bf16 hx = __float2bfloat16(x), hy = __float2bfloat16(y);
    bf16 lx = __float2bfloat16(x - __bfloat162float(hx));
    bf16 ly = __float2bfloat16(y - __bfloat162float(hy));
    H = (uint32_t)bfraw(hx) | ((uint32_t)bfraw(hy) << 16);
    L = (uint32_t)bfraw(lx) | ((uint32_t)bfraw(ly) << 16);
}

__device__ __forceinline__ uint32_t a_off(int row, int kbyte) {
    int p = row >> 1;
    int c = (row & 1) * 4 + (kbyte >> 4);
    return (uint32_t)p * 128 + (uint32_t)((c ^ (p & 7)) * 16) + (kbyte & 15);
}
__device__ __forceinline__ uint32_t b_off(int r, int nbyte) {
    int q = nbyte >> 7;
    int c = (nbyte & 127) >> 4;
    return (uint32_t)q * 4096 + (uint32_t)r * 128 + (uint32_t)((c ^ (r & 7)) * 16) + (nbyte & 15);
}

// grid-wide barrier for all-resident launches (n = gridDim total blocks)
__device__ __forceinline__ void grid_bar(int idx, unsigned int n) {
    __syncthreads();
    if (threadIdx.x == 0) {
        __threadfence();
        atomicAdd(&g_barA[idx], 1u);
        while (*((volatile unsigned int*)&g_barA[idx]) < n) __nanosleep(64);
        __threadfence();
        unsigned int d = atomicAdd(&g_barD[idx], 1u);
        if (d == n - 1) {                       // all blocks passed the spin
            *((volatile unsigned int*)&g_barA[idx]) = 0;
            __threadfence();
            *((volatile unsigned int*)&g_barD[idx]) = 0;
        }
    }
    __syncthreads();
}

// ---------------- conversions ----------------
__global__ void conv_acts(const float* __restrict__ q, const float* __restrict__ k,
                          const float* __restrict__ v) {
    int zz = blockIdx.y;
    const float* src = zz == 0 ? q : zz == 1 ? k : v;
    int idx = blockIdx.x * 256 + threadIdx.x;
    int m = idx >> 7;
    int u0 = (idx & 127) << 3;
    const float4* s = reinterpret_cast<const float4*>(src + ((size_t)m << 10) + u0);
    float4 a = s[0], b = s[1];
    uint32_t h[4], l[4];
    split2(a.x, a.y, h[0], l[0]); split2(a.z, a.w, h[1], l[1]);
    split2(b.x, b.y, h[2], l[2]); split2(b.z, b.w, h[3], l[3]);
    if (zz < 2) {
        char* hi = zz == 0 ? g_qh : g_kh;
        char* lo = zz == 0 ? g_ql : g_kl;
        size_t tile = ((size_t)(m >> 7) * 32 + (u0 >> 5)) * TA;
        uint32_t off = a_off(m & 127, (u0 & 31) * 2);
        *reinterpret_cast<uint4*>(hi + tile + off) = make_uint4(h[0], h[1], h[2], h[3]);
        *reinterpret_cast<uint4*>(lo + tile + off) = make_uint4(l[0], l[1], l[2], l[3]);
    } else {
        int batch = m >> 12, sloc = m & 4095;
        size_t tile = ((size_t)(batch * 8 + (u0 >> 7)) * 128 + (sloc >> 5)) * TBB;
        uint32_t off = b_off(sloc & 31, (u0 & 127) * 2);
        *reinterpret_cast<uint4*>(g_vbh + tile + off) = make_uint4(h[0], h[1], h[2], h[3]);
        *reinterpret_cast<uint4*>(g_vbl + tile + off) = make_uint4(l[0], l[1], l[2], l[3]);
    }
}
__global__ void conv_ws(const float* __restrict__ Wk, const float* __restrict__ Wo,
                        const float* __restrict__ Wq, const float* __restrict__ Wv) {
    int zz = blockIdx.y;
    const float* W = zz == 0 ? Wk : zz == 1 ? Wo : zz == 2 ? Wq : Wv;
    int idx = blockIdx.x * 256 + threadIdx.x;
    int r = idx >> 7;
    int c0 = (idx & 127) << 3;
    const float4* s = reinterpret_cast<const float4*>(W + ((size_t)r << 10) + c0);
    float4 a = s[0], b = s[1];
    uint32_t h[4], l[4];
    split2(a.x, a.y, h[0], l[0]); split2(a.z, a.w, h[1], l[1]);
    split2(b.x, b.y, h[2], l[2]); split2(b.z, b.w, h[3], l[3]);
    if (zz < 2) {
        char* hi = zz == 0 ? g_wkh : g_woh;
        char* lo = zz == 0 ? g_wkl : g_wol;
        size_t tile = ((size_t)(c0 >> 7) * 32 + (r >> 5)) * TBB;
        uint32_t off = b_off(r & 31, (c0 & 127) * 2);
        *reinterpret_cast<uint4*>(hi + tile + off) = make_uint4(h[0], h[1], h[2], h[3]);
        *reinterpret_cast<uint4*>(lo + tile + off) = make_uint4(l[0], l[1], l[2], l[3]);
    } else {
        char* hi = zz == 2 ? g_wqh : g_wvh;
        char* lo = zz == 2 ? g_wql : g_wvl;
        size_t tile = ((size_t)(r >> 7) * 32 + (c0 >> 5)) * TA;
        uint32_t off = a_off(r & 127, (c0 & 31) * 2);
        *reinterpret_cast<uint4*>(hi + tile + off) = make_uint4(h[0], h[1], h[2], h[3]);
        *reinterpret_cast<uint4*>(lo + tile + off) = make_uint4(l[0], l[1], l[2], l[3]);
    }
}

// ---------------- shared GEMM mainloop ----------------
__device__ __forceinline__ void refill(uint32_t st0, uint32_t sb, int s,
        const char* Abh, const char* Abl, const char* Bbh, const char* Bbl, int c) {
    MBARRIER_EXPECT_TX(sb + 8 * s, STG);
    uint32_t d = st0 + s * STG;
    bulk_g2s(d,            Abh + (size_t)c * TA,  TA,  sb + 8 * s);
    bulk_g2s(d + TA,       Abl + (size_t)c * TA,  TA,  sb + 8 * s);
    bulk_g2s(d + 2 * TA,   Bbh + (size_t)c * TBB, TBB, sb + 8 * s);
    bulk_g2s(d + 2*TA+TBB, Bbl + (size_t)c * TBB, TBB, sb + 8 * s);
}

__device__ __forceinline__ void gemm_core(
        const char* __restrict__ Abh, const char* __restrict__ Abl,
        const char* __restrict__ Bbh, const char* __restrict__ Bbl,
        int kch, uint32_t sb, uint32_t st0, float acc[4][4][4]) {
    const int tid = threadIdx.x, lane = tid & 31, wid = tid >> 5;
    const int wm = wid >> 2, wn = wid & 3;
    const int i = lane & 15, h = lane >> 4;

    if (tid == 0)
        for (int s = 0; s < STAGES; ++s) MBARRIER_INIT(sb + 8 * s, 1);
    __syncthreads();

    if (tid == 0) {
        int np = STAGES < kch ? STAGES : kch;
        for (int s = 0; s < np; ++s) refill(st0, sb, s, Abh, Abl, Bbh, Bbl, s);
    }

#pragma unroll
    for (int ii = 0; ii < 4; ii++)
#pragma unroll
        for (int j = 0; j < 4; j++)
#pragma unroll
            for (int r = 0; r < 4; r++) acc[ii][j][r] = 0.0f;

    const uint32_t aBase = (uint32_t)wm * 4096 + (uint32_t)(i >> 1) * 128;
    const int xA = (i >> 1) & 7;
    const int cA0 = (i & 1) * 4 + h;
    const uint32_t qOff = (uint32_t)(wn >> 1) * 4096;
    const int xB = lane & 7;
    const uint32_t pj0 = (uint32_t)((((wn & 1) * 4 + h)     ^ xB) * 16);
    const uint32_t pj1 = (uint32_t)((((wn & 1) * 4 + h + 2) ^ xB) * 16);
    const uint32_t bRow = (uint32_t)i * 128;

    int s = 0, pf = 0;
    for (int c = 0; c < kch; ++c) {
        MBARRIER_WAIT_PARITY(sb + 8 * s, pf);
        uint32_t sa = st0 + s * STG;
#pragma unroll
        for (int k16 = 0; k16 < 2; ++k16) {
            uint32_t bb = sa + 2 * TA + qOff + bRow + k16 * 2048;
            uint32_t bh[4][2], bl4[4][2], t[4];
            ldsm4t(t, bb + pj0);        bh[0][0]=t[0]; bh[0][1]=t[1]; bh[1][0]=t[2]; bh[1][1]=t[3];
            ldsm4t(t, bb + pj1);        bh[2][0]=t[0]; bh[2][1]=t[1]; bh[3][0]=t[2]; bh[3][1]=t[3];
            ldsm4t(t, bb + TBB + pj0);  bl4[0][0]=t[0]; bl4[0][1]=t[1]; bl4[1][0]=t[2]; bl4[1][1]=t[3];
            ldsm4t(t, bb + TBB + pj1);  bl4[2][0]=t[0]; bl4[2][1]=t[1]; bl4[3][0]=t[2]; bl4[3][1]=t[3];
            uint32_t aoff = (uint32_t)(((cA0 + k16 * 2) ^ xA) * 16);
            uint32_t ab = sa + aBase + aoff;
#pragma unroll
            for (int mf = 0; mf < 4; ++mf) {
                uint32_t ah[4], al4[4];
                ldsm4(ah, ab + mf * 1024);
                ldsm4(al4, ab + TA + mf * 1024);
#pragma unroll
                for (int nf = 0; nf < 4; ++nf) {
                    mma16816(acc[mf][nf], ah, bh[nf]);
                    mma16816(acc[mf][nf], al4, bh[nf]);
                    mma16816(acc[mf][nf], ah, bl4[nf]);
                }
            }
        }
        __syncthreads();
        if (tid == 0 && c + STAGES < kch)
            refill(st0, sb, s, Abh, Abl, Bbh, Bbl, c + STAGES);
        if (++s == STAGES) { s = 0; pf ^= 1; }
    }
}

// ---------------- epilogue helpers ----------------
__device__ __forceinline__ void epi_alayout(float acc[4][4][4], char* outH, char* outL,
                                            size_t mtile_base) {
    const int lane = threadIdx.x & 31, wid = threadIdx.x >> 5;
    const int wm = wid >> 2, wn = wid & 3;
    const int g = lane >> 2, tg = lane & 3;
    size_t mtile = (mtile_base + wn) * TA;
#pragma unroll
    for (int mf = 0; mf < 4; ++mf)
#pragma unroll
        for (int nf = 0; nf < 4; ++nf)
#pragma unroll
            for (int rh = 0; rh < 2; ++rh) {
                int row = wm * 64 + mf * 16 + g + rh * 8;
                uint32_t hw, lw;
                split2(acc[mf][nf][rh * 2], acc[mf][nf][rh * 2 + 1], hw, lw);
                uint32_t off = a_off(row, nf * 16 + tg * 4);
                *reinterpret_cast<uint32_t*>(outH + mtile + off) = hw;
                *reinterpret_cast<uint32_t*>(outL + mtile + off) = lw;
            }
}
__device__ __forceinline__ void epi_blayout(float acc[4][4][4], char* outH, char* outL,
                                            size_t nkbase, int m0) {
    const int lane = threadIdx.x & 31, wid = threadIdx.x >> 5;
    const int wm = wid >> 2, wn = wid & 3;
    const int g = lane >> 2, tg = lane & 3;
#pragma unroll
    for (int mf = 0; mf < 4; ++mf)
#pragma unroll
        for (int rh = 0; rh < 2; ++rh) {
            int row = wm * 64 + mf * 16 + g + rh * 8;
            int kloc = m0 + row;
            size_t tile = (nkbase + (kloc >> 5)) * TBB;
#pragma unroll
            for (int nf = 0; nf < 4; ++nf) {
                uint32_t hw, lw;
                split2(acc[mf][nf][rh * 2], acc[mf][nf][rh * 2 + 1], hw, lw);
                uint32_t off = b_off(kloc & 31, (wn * 32 + nf * 8 + tg * 2) * 2);
                *reinterpret_cast<uint32_t*>(outH + tile + off) = hw;
                *reinterpret_cast<uint32_t*>(outL + tile + off) = lw;
            }
        }
}

// ---------------- GEMM kernels ----------------
// Merged: blocks 0..1023 do pk3T tiles; blocks 1024..1087 do WvWo tiles (tail-fill).
__global__ void __launch_bounds__(256, 2)
projkB_gemm(const float* __restrict__ mask) {
    extern __shared__ __align__(1024) char smem[];
    uint32_t sb = s2u(smem), st0 = sb + 1024;
    const int tid = threadIdx.x, lane = tid & 31, wid = tid >> 5;
    const int wm = wid >> 2, wn = wid & 3;
    const int g = lane >> 2, tg = lane & 3;
    const int bid = blockIdx.x;

    if (bid >= 1024) {
        // WvWo = Wv @ Wo -> B-layout
        int b2 = bid - 1024;
        int by = b2 >> 3, bx = b2 & 7;
        float acc[4][4][4];
        gemm_core(g_wvh + (size_t)by * 32 * TA, g_wvl + (size_t)by * 32 * TA,
                  g_woh + (size_t)bx * 32 * TBB, g_wol + (size_t)bx * 32 * TBB,
                  32, sb, st0, acc);
        epi_blayout(acc, g_wvwoh, g_wvwol, (size_t)bx * 32, by * 128);
        return;
    }

    const int by = bid >> 3, bx = bid & 7;     // by 0..127 global M-tile
    const int m0 = by * 128;

    float acc[4][4][4];
    gemm_core(g_kh + (size_t)by * 32 * TA, g_kl + (size_t)by * 32 * TA,
              g_wkh + (size_t)bx * 32 * TBB, g_wkl + (size_t)bx * 32 * TBB,
              32, sb, st0, acc);
    __syncthreads();

    uint32_t shh = st0, sll = st0 + 34816;
#pragma unroll
    for (int mf = 0; mf < 4; ++mf)
#pragma unroll
        for (int rh = 0; rh < 2; ++rh) {
            int row = wm * 64 + mf * 16 + g + rh * 8;
            float mv = mask[m0 + row];
#pragma unroll
            for (int nf = 0; nf < 4; ++nf) {
                float v0 = acc[mf][nf][rh * 2] * mv;
                float v1 = acc[mf][nf][rh * 2 + 1] * mv;
                v0 = v0 / (1.0f + __expf(-v0)) * mv;
                v1 = v1 / (1.0f + __expf(-v1)) * mv;
                uint32_t hw, lw;
                split2(v0, v1, hw, lw);
                uint32_t a = (uint32_t)row * 272 + (wn * 32 + nf * 8 + tg * 2) * 2;
                asm volatile("st.shared.b32 [%0], %1;" :: "r"(shh + a), "r"(hw) : "memory");
                asm volatile("st.shared.b32 [%0], %1;" :: "r"(sll + a), "r"(lw) : "memory");
            }
        }
    __syncthreads();
    int u = tid & 127;
    int sh2 = (tid >> 7) * 64;
    int bt = by >> 5;
    int kc0 = (m0 & 4095) >> 5;
#pragma unroll
    for (int c8 = 0; c8 < 8; ++c8) {
        int s0 = sh2 + c8 * 8;
        uint32_t hw[4], lw[4];
#pragma unroll
        for (int p = 0; p < 4; ++p) {
            unsigned short h0, h1, l0, l1;
            uint32_t a0 = (uint32_t)(s0 + 2 * p) * 272 + (uint32_t)u * 2;
            uint32_t a1 = a0 + 272;
            asm volatile("ld.shared.b16 %0, [%1];" : "=h"(h0) : "r"(shh + a0));
            asm volatile("ld.shared.b16 %0, [%1];" : "=h"(h1) : "r"(shh + a1));
            asm volatile("ld.shared.b16 %0, [%1];" : "=h"(l0) : "r"(sll + a0));
            asm volatile("ld.shared.b16 %0, [%1];" : "=h"(l1) : "r"(sll + a1));
            hw[p] = (uint32_t)h0 | ((uint32_t)h1 << 16);
            lw[p] = (uint32_t)l0 | ((uint32_t)l1 << 16);
        }
        size_t tile = ((size_t)(bt * 8 + bx) * 128 + kc0 + (s0 >> 5)) * TA;
        uint32_t off = a_off(u, (s0 & 31) * 2);
        *reinterpret_cast<uint4*>(g_pkth + tile + off) = make_uint4(hw[0], hw[1], hw[2], hw[3]);
        *reinterpret_cast<uint4*>(g_pktl + tile + off) = make_uint4(lw[0], lw[1], lw[2], lw[3]);
    }
}

// Fused kvr -> kvo -> wqkvo, 256 blocks (all resident), grid barriers between phases.
__global__ void __launch_bounds__(256, 2)
kvx_gemm() {
    extern __shared__ __align__(1024) char smem[];
    uint32_t sb = s2u(smem), st0 = sb + 1024;
    const int bid = blockIdx.x;
    const int b = bid >> 6, by = (bid >> 3) & 7, bx = bid & 7;

    float acc[4][4][4];
    // Phase 1: kvr[b] = pk3T[b] @ v[b]  (K=4096)
    gemm_core(g_pkth + (size_t)(b * 8 + by) * 128 * TA, g_pktl + (size_t)(b * 8 + by) * 128 * TA,
              g_vbh + (size_t)(b * 8 + bx) * 128 * TBB, g_vbl + (size_t)(b * 8 + bx) * 128 * TBB,
              128, sb, st0, acc);
    epi_alayout(acc, g_kvrh, g_kvrl, (size_t)(b * 8 + by) * 32 + bx * 4);

    grid_bar(0, 256);

    // Phase 2: kvo[b] = kvr[b] @ WvWo
    gemm_core(g_kvrh + (size_t)(b * 8 + by) * 32 * TA, g_kvrl + (size_t)(b * 8 + by) * 32 * TA,
              g_wvwoh + (size_t)bx * 32 * TBB, g_wvwol + (size_t)bx * 32 * TBB,
              32, sb, st0, acc);
    epi_blayout(acc, g_kvoh, g_kvol, (size_t)(b * 8 + bx) * 32, by * 128);

    grid_bar(1, 256);

    // Phase 3: fin[b] = Wq @ kvo[b]
    gemm_core(g_wqh + (size_t)by * 32 * TA, g_wql + (size_t)by * 32 * TA,
              g_kvoh + (size_t)(b * 8 + bx) * 32 * TBB, g_kvol + (size_t)(b * 8 + bx) * 32 * TBB,
              32, sb, st0, acc);
    epi_blayout(acc, g_finh, g_finl, (size_t)(b * 8 + bx) * 32, by * 128);
}

// out[b] = q[b] @ fin[b] -> f32
__global__ void __launch_bounds__(256, 2)
final_gemm(float* __restrict__ outF) {
    extern __shared__ __align__(1024) char smem[];
    uint32_t sb = s2u(smem), st0 = sb + 1024;
    const int tid = threadIdx.x, lane = tid & 31, wid = tid >> 5;
    const int wm = wid >> 2, wn = wid & 3;
    const int bx = blockIdx.x, by = blockIdx.y, z = blockIdx.z;
    const int g = lane >> 2, tg = lane & 3;
    const int mb = z * 32 + by;
    const int n0 = bx * 128;

    float acc[4][4][4];
    gemm_core(g_qh + (size_t)mb * 32 * TA, g_ql + (size_t)mb * 32 * TA,
              g_finh + (size_t)(z * 8 + bx) * 32 * TBB, g_finl + (size_t)(z * 8 + bx) * 32 * TBB,
              32, sb, st0, acc);

#pragma unroll
    for (int mf = 0; mf < 4; ++mf)
#pragma unroll
        for (int nf = 0; nf < 4; ++nf)
#pragma unroll
            for (int rh = 0; rh < 2; ++rh) {
                int row = wm * 64 + mf * 16 + g + rh * 8;
                int gcol = n0 + wn * 32 + nf * 8 + tg * 2;
                float2 v = make_float2(acc[mf][nf][rh * 2], acc[mf][nf][rh * 2 + 1]);
                *reinterpret_cast<float2*>(outF + ((size_t)mb * 128 + row) * 1024 + gcol) = v;
            }
}

// ---------------- launch ----------------
extern "C" void kernel_launch(void* const* d_in, const int* in_sizes, int n_in,
                              void* d_out, int out_size) {
    const float* query = (const float*)d_in[0];
    const float* key   = (const float*)d_in[1];
    const float* value = (const float*)d_in[2];
    const float* mask  = (const float*)d_in[3];
    const float* Wk    = (const float*)d_in[4];
    const float* Wv    = (const float*)d_in[5];
    const float* Wq    = (const float*)d_in[6];
    const float* Wo    = (const float*)d_in[7];
    float* out = (float*)d_out;

    static bool attr_done = false;
    if (!attr_done) {
        cudaFuncSetAttribute(projkB_gemm, cudaFuncAttributeMaxDynamicSharedMemorySize, SMEM_SZ);
        cudaFuncSetAttribute(kvx_gemm,    cudaFuncAttributeMaxDynamicSharedMemorySize, SMEM_SZ);
        cudaFuncSetAttribute(final_gemm,  cudaFuncAttributeMaxDynamicSharedMemorySize, SMEM_SZ);
        attr_done = true;
    }

    conv_acts<<<dim3(8192, 3), 256>>>(query, key, value);
    conv_ws<<<dim3(512, 4), 256>>>(Wk, Wo, Wq, Wv);

    projkB_gemm<<<1088, 256, SMEM_SZ>>>(mask);
    kvx_gemm<<<256, 256, SMEM_SZ>>>();
    final_gemm<<<dim3(8, 32, 4), 256, SMEM_SZ>>>(out);
}